// round 13
// baseline (speedup 1.0000x reference)
#include <cuda_runtime.h>
#include <cstdint>
#include <math.h>

#define BATCH   2
#define SEQLEN  4096
#define DMODEL  1024
#define DINNER  2048
#define NHEADS  32
#define HEADDIM 64
#define DSTATE  64
#define CONVDIM 2176            // DINNER + 2*DSTATE
#define DINPROJ 4256            // 2*DINNER + 2*DSTATE + NHEADS
#define BL      8192            // BATCH*SEQLEN
#define CHUNK   64
#define NCHUNK  (SEQLEN / CHUNK)   // 64

// ---------------- scratch (static device globals: no allocations) ----------
__device__ float    g_zx  [(size_t)BL * DINPROJ];
__device__ float    g_xbca[(size_t)BL * CONVDIM];
__device__ float    g_dt  [(size_t)BL * NHEADS];
__device__ float    g_y   [(size_t)BL * DINNER];
__device__ float    g_hc  [(size_t)BATCH * NHEADS * NCHUNK * 64 * 64]; // [bh][c][p][n]
// pre-split bf16 hi/lo operand planes
__device__ uint16_t g_uh  [(size_t)BL * DMODEL];
__device__ uint16_t g_ul  [(size_t)BL * DMODEL];
__device__ uint16_t g_ynh [(size_t)BL * DINNER];
__device__ uint16_t g_ynl [(size_t)BL * DINNER];
__device__ uint16_t g_wih [(size_t)DINPROJ * DMODEL];
__device__ uint16_t g_wil [(size_t)DINPROJ * DMODEL];
__device__ uint16_t g_woh [(size_t)DMODEL * DINNER];
__device__ uint16_t g_wol [(size_t)DMODEL * DINNER];

// ---------------- helpers ---------------------------------------------------
__device__ __forceinline__ uint32_t smem_u32(const void* p) {
    uint32_t a;
    asm("{ .reg .u64 t; cvta.to.shared.u64 t, %1; cvt.u32.u64 %0, t; }"
        : "=r"(a) : "l"(p));
    return a;
}
__device__ __forceinline__ float tf32_rna(float a) {
    uint32_t u;
    asm("cvt.rna.tf32.f32 %0, %1;" : "=r"(u) : "f"(a));
    return __uint_as_float(u);
}
__device__ __forceinline__ void tf32_split(float v, uint32_t& hi, uint32_t& lo) {
    float h = tf32_rna(v);
    hi = __float_as_uint(h);
    lo = __float_as_uint(tf32_rna(v - h));
}
// pack two f32 -> bf16x2 (first arg in LOW half)
__device__ __forceinline__ uint32_t packbf(float lo, float hi) {
    uint32_t r;
    asm("cvt.rn.bf16x2.f32 %0, %1, %2;" : "=r"(r) : "f"(hi), "f"(lo));
    return r;
}
// split float4 -> hi uint2 / lo uint2 (bf16x2 pairs)
__device__ __forceinline__ void split4(float4 v, uint2& hi, uint2& lo) {
    uint32_t h01 = packbf(v.x, v.y);
    uint32_t h23 = packbf(v.z, v.w);
    float rx = v.x - __uint_as_float(h01 << 16);
    float ry = v.y - __uint_as_float(h01 & 0xffff0000u);
    float rz = v.z - __uint_as_float(h23 << 16);
    float rw = v.w - __uint_as_float(h23 & 0xffff0000u);
    hi = make_uint2(h01, h23);
    lo = make_uint2(packbf(rx, ry), packbf(rz, rw));
}

#define MMA_TF32(d, a, b0, b1) \
    asm volatile("mma.sync.aligned.m16n8k8.row.col.f32.tf32.tf32.f32 " \
        "{%0,%1,%2,%3}, {%4,%5,%6,%7}, {%8,%9}, {%0,%1,%2,%3};" \
        : "+f"((d)[0]), "+f"((d)[1]), "+f"((d)[2]), "+f"((d)[3]) \
        : "r"((a)[0]), "r"((a)[1]), "r"((a)[2]), "r"((a)[3]), \
          "r"(b0), "r"(b1))

#define MMA_BF16(d, a, b0, b1) \
    asm volatile("mma.sync.aligned.m16n8k16.row.col.f32.bf16.bf16.f32 " \
        "{%0,%1,%2,%3}, {%4,%5,%6,%7}, {%8,%9}, {%0,%1,%2,%3};" \
        : "+f"((d)[0]), "+f"((d)[1]), "+f"((d)[2]), "+f"((d)[3]) \
        : "r"((a)[0]), "r"((a)[1]), "r"((a)[2]), "r"((a)[3]), \
          "r"(b0), "r"(b1))

#define LDSM_X4(r, addr) \
    asm volatile("ldmatrix.sync.aligned.m8n8.x4.shared.b16 {%0,%1,%2,%3}, [%4];" \
        : "=r"((r)[0]), "=r"((r)[1]), "=r"((r)[2]), "=r"((r)[3]) : "r"(addr))

#define CP_ASYNC16(dst, src) \
    asm volatile("cp.async.ca.shared.global [%0], [%1], 16;" \
        :: "r"(dst), "l"(src) : "memory")
#define CP_ASYNC16_P(dst, src, nbytes) \
    asm volatile("cp.async.ca.shared.global [%0], [%1], 16, %2;" \
        :: "r"(dst), "l"(src), "r"(nbytes) : "memory")
#define CP_ASYNC4(dst, src) \
    asm volatile("cp.async.ca.shared.global [%0], [%1], 4;" \
        :: "r"(dst), "l"(src) : "memory")
#define CP_COMMIT() asm volatile("cp.async.commit_group;" ::: "memory")
#define CP_WAIT0()  asm volatile("cp.async.wait_group 0;" ::: "memory")
#define CP_WAIT1()  asm volatile("cp.async.wait_group 1;" ::: "memory")

// -------- weight split kernel: fp32 -> bf16 hi/lo ---------------------------
__global__ void __launch_bounds__(256) wsplit_kernel(const float* __restrict__ src,
                                                     uint16_t* __restrict__ dh,
                                                     uint16_t* __restrict__ dl,
                                                     int n4)
{
    int i = blockIdx.x * 256 + threadIdx.x;
    if (i < n4) {
        float4 v = ((const float4*)src)[i];
        uint2 hi, lo;
        split4(v, hi, lo);
        ((uint2*)dh)[i] = hi;
        ((uint2*)dl)[i] = lo;
    }
}

// =============== bf16x3 emulated-fp32 NT GEMM (cp.async + LDSM) ============
// Operands pre-split in global (bf16 hi/lo). Staging = pure cp.async.
// occ 2 CTAs/SM, 2-stage ring, ldmatrix fragment loads.
#define KT        32
#define RSU       20                       // row stride (uint32 pairs, 80 B)
#define PL_AHI    0
#define PL_ALO    2560
#define PL_BHI    5120
#define PL_BLO    7680
#define STAGE_U   10240                    // uint32 per stage
#define SMEM_DYN  (2 * STAGE_U * 4)        // 81920 bytes

template<int N, int K, bool SECOND>
__global__ void __launch_bounds__(256, 2) gemm_tc(const float* __restrict__ resid,
                                                  float* __restrict__ outp)
{
    extern __shared__ uint32_t smu[];
    const uint16_t* __restrict__ Ah = SECOND ? g_ynh : g_uh;
    const uint16_t* __restrict__ Al = SECOND ? g_ynl : g_ul;
    const uint16_t* __restrict__ Wh = SECOND ? g_woh : g_wih;
    const uint16_t* __restrict__ Wl = SECOND ? g_wol : g_wil;
    float* __restrict__ Cptr        = SECOND ? outp : g_zx;

    int tid = threadIdx.x;
    int wid = tid >> 5, lane = tid & 31;
    int bm = blockIdx.y, bn = blockIdx.x;

    uint32_t sb = smem_u32(smu);

    // staging: thread copies 2 (row, chunk) slots x 4 planes per k-tile
    int rA = tid >> 2, cA = (tid & 3) * 16;       // row 0..63, byte chunk
    const int NKT = K / KT;
    auto issue = [&](int kt) {
        if (kt < NKT) {
            uint32_t dst = sb + (uint32_t)(kt & 1) * (STAGE_U * 4);
            #pragma unroll
            for (int i = 0; i < 2; i++) {
                int row = rA + i * 64;
                uint32_t so = (uint32_t)(row * (RSU * 4)) + cA;
                size_t ao = (size_t)(bm * 128 + row) * K + kt * KT + (cA >> 1);
                CP_ASYNC16(dst + PL_AHI * 4 + so, Ah + ao);
                CP_ASYNC16(dst + PL_ALO * 4 + so, Al + ao);
                int nrow = bn * 128 + row;
                int nb = (nrow < N) ? 16 : 0;
                size_t bo = (size_t)nrow * K + kt * KT + (cA >> 1);
                CP_ASYNC16_P(dst + PL_BHI * 4 + so, Wh + bo, nb);
                CP_ASYNC16_P(dst + PL_BLO * 4 + so, Wl + bo, nb);
            }
        }
        CP_COMMIT();
    };

    int wm = wid >> 1, wn = wid & 1;
    int g = lane >> 2, t4 = lane & 3;

    // ldmatrix lane-address offsets (bytes, within a stage, kb=0)
    uint32_t aoff = (uint32_t)(((wm * 32 + (lane & 15)) * RSU + 4 * (lane >> 4)) * 4);
    uint32_t boff = (uint32_t)(((wn * 64 + 8 * (lane >> 4) + (lane & 7)) * RSU
                                + 4 * ((lane >> 3) & 1)) * 4);

    float d[2][8][4];
    #pragma unroll
    for (int mt = 0; mt < 2; mt++)
        #pragma unroll
        for (int nt = 0; nt < 8; nt++)
            #pragma unroll
            for (int j = 0; j < 4; j++) d[mt][nt][j] = 0.f;

    issue(0);

    #pragma unroll 1
    for (int kt = 0; kt < NKT; ++kt) {
        issue(kt + 1);
        if (kt + 1 < NKT) CP_WAIT1(); else CP_WAIT0();
        __syncthreads();                       // stage kt visible to all

        uint32_t base = sb + (uint32_t)(kt & 1) * (STAGE_U * 4);
        #pragma unroll
        for (int ks = 0; ks < 2; ks++) {
            uint32_t kby = (uint32_t)(ks * 8 * 4);
            uint32_t ah[2][4], al[2][4];
            #pragma unroll
            for (int mt = 0; mt < 2; mt++) {
                uint32_t aa = base + aoff + (uint32_t)(mt * 16 * RSU * 4) + kby;
                LDSM_X4(ah[mt], aa + PL_AHI * 4);
                LDSM_X4(al[mt], aa + PL_ALO * 4);
            }
            #pragma unroll
            for (int ntp = 0; ntp < 4; ntp++) {
                uint32_t ba = base + boff + (uint32_t)(ntp * 16 * RSU * 4) + kby;
                uint32_t bh[4], bl[4];
                LDSM_X4(bh, ba + PL_BHI * 4);
                LDSM_X4(bl, ba + PL_BLO * 4);
                #pragma unroll
                for (int mt = 0; mt < 2; mt++) {
                    MMA_BF16(d[mt][2*ntp],   ah[mt], bh[0], bh[1]);
                    MMA_BF16(d[mt][2*ntp],   ah[mt], bl[0], bl[1]);
                    MMA_BF16(d[mt][2*ntp],   al[mt], bh[0], bh[1]);
                    MMA_BF16(d[mt][2*ntp+1], ah[mt], bh[2], bh[3]);
                    MMA_BF16(d[mt][2*ntp+1], ah[mt], bl[2], bl[3]);
                    MMA_BF16(d[mt][2*ntp+1], al[mt], bh[2], bh[3]);
                }
            }
        }
        __syncthreads();                       // reads done before re-fill
    }

    #pragma unroll
    for (int mt = 0; mt < 2; mt++) {
        int row = bm * 128 + wm * 32 + mt * 16 + g;
        #pragma unroll
        for (int nt = 0; nt < 8; nt++) {
            int col = bn * 128 + wn * 64 + nt * 8 + t4 * 2;
            if (col < N) {
                size_t i0 = (size_t)row * N + col;
                size_t i1 = (size_t)(row + 8) * N + col;
                float2 v0 = make_float2(d[mt][nt][0], d[mt][nt][1]);
                float2 v1 = make_float2(d[mt][nt][2], d[mt][nt][3]);
                if (SECOND) {
                    float2 r0v = *(const float2*)(resid + i0);
                    float2 r1v = *(const float2*)(resid + i1);
                    v0.x += r0v.x; v0.y += r0v.y;
                    v1.x += r1v.x; v1.y += r1v.y;
                }
                *(float2*)(Cptr + i0) = v0;
                *(float2*)(Cptr + i1) = v1;
            }
        }
    }
}

// ---------------- block reduction helper -----------------------------------
__device__ __forceinline__ float block_sum256(float v, float* sh) {
    #pragma unroll
    for (int o = 16; o; o >>= 1) v += __shfl_xor_sync(0xffffffffu, v, o);
    int lane = threadIdx.x & 31, wid = threadIdx.x >> 5;
    __syncthreads();
    if (lane == 0) sh[wid] = v;
    __syncthreads();
    float tt = 0.f;
    #pragma unroll
    for (int j = 0; j < 8; j++) tt += sh[j];
    return tt;
}

// ---------------- 1) LayerNorm (writes bf16 hi/lo planes) -------------------
__global__ void __launch_bounds__(256) ln_kernel(const float* __restrict__ x,
                                                 const float* __restrict__ w,
                                                 const float* __restrict__ bparm)
{
    __shared__ float sh[8];
    int row = blockIdx.x, tid = threadIdx.x;
    const float4* xr = (const float4*)(x + (size_t)row * DMODEL);
    float4 v = xr[tid];
    float s  = v.x + v.y + v.z + v.w;
    float mu = block_sum256(s, sh) * (1.f / DMODEL);
    float d0 = v.x - mu, d1 = v.y - mu, d2 = v.z - mu, d3 = v.w - mu;
    float vs = d0*d0 + d1*d1 + d2*d2 + d3*d3;
    float var = block_sum256(vs, sh) * (1.f / DMODEL);
    float inv = rsqrtf(var + 1e-5f);
    float4 wv = ((const float4*)w)[tid];
    float4 bv = ((const float4*)bparm)[tid];
    float4 o;
    o.x = d0 * inv * wv.x + bv.x;
    o.y = d1 * inv * wv.y + bv.y;
    o.z = d2 * inv * wv.z + bv.z;
    o.w = d3 * inv * wv.w + bv.w;
    uint2 hi, lo;
    split4(o, hi, lo);
    size_t idx = (size_t)row * DMODEL + tid * 4;
    *(uint2*)(g_uh + idx) = hi;
    *(uint2*)(g_ul + idx) = lo;
}

// ---------------- 3) causal conv(4)+SiLU, fused softplus(dt) ---------------
__global__ void __launch_bounds__(256) conv_dt_kernel(const float* __restrict__ conv_w,
                                                      const float* __restrict__ conv_b,
                                                      const float* __restrict__ dt_bias)
{
    int i = blockIdx.y;
    int c = blockIdx.x * 256 + threadIdx.x;
    int b = i >> 12;
    int l = i & 4095;
    if (c < CONVDIM) {
        float w0 = conv_w[c*4+0], w1 = conv_w[c*4+1];
        float w2 = conv_w[c*4+2], w3 = conv_w[c*4+3];
        const float* col = g_zx + (size_t)(b << 12) * DINPROJ + DINNER + c;
        float s = conv_b[c];
        if (l >= 3) s += col[(size_t)(l-3) * DINPROJ] * w0;
        if (l >= 2) s += col[(size_t)(l-2) * DINPROJ] * w1;
        if (l >= 1) s += col[(size_t)(l-1) * DINPROJ] * w2;
        s += col[(size_t)l * DINPROJ] * w3;
        s = s / (1.f + expf(-s));
        g_xbca[(size_t)i * CONVDIM + c] = s;
    } else if (c < CONVDIM + NHEADS) {
        int hh = c - CONVDIM;
        float v = g_zx[(size_t)i * DINPROJ + (DINNER + CONVDIM) + hh] + dt_bias[hh];
        g_dt[(size_t)i * NHEADS + hh] = (v > 20.f) ? v : log1pf(expf(v));
    }
}

// -------- warp-0 inclusive scan of 64 s-values (dt*Ah) -> cum[64] ----------
__device__ __forceinline__ void scan64(const float* dtv, float Ah, float* cum, int tid) {
    if (tid < 32) {
        float a = dtv[tid] * Ah;
        float b = dtv[32 + tid] * Ah;
        #pragma unroll
        for (int o = 1; o < 32; o <<= 1) {
            float ta = __shfl_up_sync(0xffffffffu, a, o);
            float tb = __shfl_up_sync(0xffffffffu, b, o);
            if (tid >= o) { a += ta; b += tb; }
        }
        float totA = __shfl_sync(0xffffffffu, a, 31);
        cum[tid]      = a;
        cum[32 + tid] = totA + b;
    }
}

// ---------------- 4a) S1: sequential chunk-state pass (tf32x3 MMA) ---------
#define S1_X    0                           // X [64][68]
#define S1_B    4352                        // B [64][36]
#define S1_DT   6656                        // dt[64]
#define S1_BUF  6720
#define S1_W    (2 * S1_BUF)                // w[64]
#define S1_CUM  (S1_W + 64)                 // cum[64]
#define S1_SMEMF (S1_CUM + 64)
#define S1_SMEMB (S1_SMEMF * 4)

__global__ void __launch_bounds__(256) s1_kernel(const float* __restrict__ A_log)
{
    extern __shared__ float sm[];
    int bx = blockIdx.x;
    int b = bx >> 6, h = (bx >> 1) & 31, nh = bx & 1;
    int tid = threadIdx.x;
    int wid = tid >> 5, lane = tid & 31;
    int wm = wid & 1, wn = wid >> 1;
    int g = lane >> 2, t4 = lane & 3;
    int nb0 = wm * 16;
    float Ah = -expf(A_log[h]);

    float* w   = sm + S1_W;
    float* cum = sm + S1_CUM;
    uint32_t sbase = smem_u32(sm);

    const float* base = g_xbca + (size_t)b * SEQLEN * CONVDIM;
    const float* dtb  = g_dt   + (size_t)b * SEQLEN * NHEADS + h;

    auto issue = [&](int c) {
        if (c < NCHUNK) {
            uint32_t dst = sbase + (uint32_t)(c & 1) * (S1_BUF * 4);
            const float* rowb = base + (size_t)c * CHUNK * CONVDIM;
            #pragma unroll
            for (int i = 0; i < 4; i++) {
                int f4 = tid + i * 256;
                int t = f4 >> 4, j = (f4 & 15) * 4;
                CP_ASYNC16(dst + (uint32_t)(t * 68 + j) * 4,
                           rowb + (size_t)t * CONVDIM + h * 64 + j);
            }
            #pragma unroll
            for (int i = 0; i < 2; i++) {
                int f4 = tid + i * 256;
                int t = f4 >> 3, j = (f4 & 7) * 4;
                CP_ASYNC16(dst + (uint32_t)(S1_B + t * 36 + j) * 4,
                           rowb + (size_t)t * CONVDIM + 2048 + nh * 32 + j);
            }
            if (tid < 64)
                CP_ASYNC4(dst + (uint32_t)(S1_DT + tid) * 4,
                          dtb + (size_t)(c * CHUNK + tid) * NHEADS);
        }
        CP_COMMIT();
    };

    float d0[4] = {0.f, 0.f, 0.f, 0.f};
    float d1[4] = {0.f, 0.f, 0.f, 0.f};

    issue(0); issue(1);

    for (int c = 0; c < NCHUNK; c++) {
        CP_WAIT1();
        __syncthreads();
        float* S = sm + (c & 1) * S1_BUF;

        scan64(S + S1_DT, Ah, cum, tid);
        __syncthreads();

        float cl = cum[63];
        float E  = expf(cl);
        if (tid < 64) w[tid] = expf(cl - cum[tid]) * S[S1_DT + tid];

        {   // transposed carry store: g_hc[..][p][n]
            size_t hcb = (((size_t)(b * 32 + h)) * NCHUNK + c) * 4096;
            int nrow = nh * 32 + nb0 + g;
            int col0 = wn * 16 + 2 * t4;
            g_hc[hcb + (size_t)(col0    ) * 64 + nrow    ] = d0[0];
            g_hc[hcb + (size_t)(col0 + 1) * 64 + nrow    ] = d0[1];
            g_hc[hcb + (size_t)(col0    ) * 64 + nrow + 8] = d0[2];
            g_hc[hcb + (size_t)(col0 + 1) * 64 + nrow + 8] = d0[3];
            g_hc[hcb + (size_t)(col0 + 8) * 64 + nrow    ] = d1[0];
            g_hc[hcb + (size_t)(col0 + 9) * 64 + nrow    ] = d1[1];
            g_hc[hcb + (size_t)(col0 + 8) * 64 + nrow + 8] = d1[2];
            g_hc[hcb + (size_t)(col0 + 9) * 64 + nrow + 8] = d1[3];
        }
        #pragma unroll
        for (int j = 0; j < 4; j++) { d0[j] *= E; d1[j] *= E; }
        __syncthreads();

        const float* Bs = S + S1_B;
        const float* Xs = S;
        #pragma unroll
        for (int k0 = 0; k0 < 64; k0 += 8) {
            int ka = k0 + t4, kb = ka + 4;
            float wa = w[ka], wb = w[kb];
            uint32_t ahi[4], alo[4];
            tf32_split(Bs[ka * 36 + nb0 + g]     * wa, ahi[0], alo[0]);
            tf32_split(Bs[ka * 36 + nb0 + g + 8] * wa, ahi[1], alo[1]);
            tf32_split(Bs[kb * 36 + nb0 + g]     * wb, ahi[2], alo[2]);
            tf32_split(Bs[kb * 36 + nb0 + g + 8] * wb, ahi[3], alo[3]);
            {
                int p = wn * 16 + g;
                uint32_t bh0, bl0, bh1, bl1;
                tf32_split(Xs[ka * 68 + p], bh0, bl0);
                tf32_split(Xs[kb * 68 + p], bh1, bl1);
                MMA_TF32(d0, ahi, bh0, bh1);
                MMA_TF32(d0, ahi, bl0, bl1);
                MMA_TF32(d0, alo, bh0, bh1);
            }
            {
                int p = wn * 16 + 8 + g;
                uint32_t bh0, bl0, bh1, bl1;
                tf32_split(Xs[ka * 68 + p], bh0, bl0);
                tf32_split(Xs[kb * 68 + p], bh1, bl1);
                MMA_TF32(d1, ahi, bh0, bh1);
                MMA_TF32(d1, ahi, bl0, bl1);
                MMA_TF32(d1, alo, bh0, bh1);
            }
        }
        __syncthreads();
        issue(c + 2);
    }
}

// ---------------- 4b) S2: per-chunk parallel y (bf16x3 MMA) -----------------
#define P_A     0          // C hi (later G hi)
#define P_ALO   2304
#define P_B     4608
#define P_BLO   6912
#define P_C2    9216
#define P_C2LO  11520
#define P_XT    13824
#define P_XTLO  16128
#define P_HT    18432
#define P_HTLO  20736
#define P_XF    23040      // fp32 X tile [64][68]
#define P_DT2   27392
#define P_CUM2  27456
#define S2N_U   27520
#define S2N_B   (S2N_U * 4)   // 110080 bytes

__global__ void __launch_bounds__(256) s2_kernel(const float* __restrict__ A_log,
                                                 const float* __restrict__ Dp)
{
    extern __shared__ uint32_t su[];
    float* sf = (float*)su;
    int bx = blockIdx.x;
    int c = bx & 63, h = (bx >> 6) & 31, b = bx >> 11;
    int tid = threadIdx.x;
    int wid = tid >> 5, lane = tid & 31;
    int wm = wid >> 1, wn = wid & 1;        // 4x2 warp grid, warp tile 16x32
    int g = lane >> 2, t4 = lane & 3;
    float Ah = -expf(A_log[h]);
    float Dh = Dp[h];

    const float* rowb  = g_xbca + ((size_t)b * SEQLEN + c * 64) * CONVDIM;
    const float* hts   = g_hc + (((size_t)(b * 32 + h)) * NCHUNK + c) * 4096; // [p][n]

    int r  = tid >> 2;
    int cg = (tid & 3) * 16;

    auto put4 = [&](uint32_t off, int row, int col, float4 v) {
        uint2 hi, lo;
        split4(v, hi, lo);
        *(uint2*)&su[off + row * 36 + col / 2]        = hi;
        *(uint2*)&su[off + 2304 + row * 36 + col / 2] = lo;
    };

    float4 cre[4];
    #pragma unroll
    for (int i = 0; i < 4; i++) {
        int col = cg + 4 * i;
        cre[i] = *(const float4*)(rowb + (size_t)r * CONVDIM + 2112 + col);
        put4(P_A, r, col, cre[i]);
        float4 bv = *(const float4*)(rowb + (size_t)r * CONVDIM + 2048 + col);
        put4(P_B, r, col, bv);
        float4 hv = *(const float4*)(hts + (size_t)r * 64 + col);
        put4(P_HT, r, col, hv);
        float4 xv = *(const float4*)(rowb + (size_t)r * CONVDIM + h * 64 + col);
        *(float4*)&sf[P_XF + r * 68 + col] = xv;
    }
    if (tid < 64)
        sf[P_DT2 + tid] = g_dt[((size_t)b * SEQLEN + c * 64 + tid) * NHEADS + h];
    __syncthreads();

    scan64(sf + P_DT2, Ah, sf + P_CUM2, tid);
    __syncthreads();

    {
        float Et = expf(sf[P_CUM2 + r]);
        #pragma unroll
        for (int i = 0; i < 4; i++) {
            float4 v = cre[i];
            v.x *= Et; v.y *= Et; v.z *= Et; v.w *= Et;
            put4(P_C2, r, cg + 4 * i, v);
        }
    }
    {
        int p = tid & 63, tq = tid >> 6;
        #pragma unroll
        for (int j2 = 0; j2 < 2; j2++) {
            float xv[8];
            #pragma unroll
            for (int k = 0; k < 8; k++)
                xv[k] = sf[P_XF + (tq * 16 + j2 * 8 + k) * 68 + p];
            uint32_t hi[4], lo[4];
            #pragma unroll
            for (int q = 0; q < 4; q++) {
                hi[q] = packbf(xv[2*q], xv[2*q+1]);
                float r0 = xv[2*q]   - __uint_as_float(hi[q] << 16);
                float r1 = xv[2*q+1] - __uint_as_float(hi[q] & 0xffff0000u);
                lo[q] = packbf(r0, r1);
            }
            int pi = tq * 8 + j2 * 4;
            *(uint2*)&su[P_XT   + p * 36 + pi]     = make_uint2(hi[0], hi[1]);
            *(uint2*)&su[P_XT   + p * 36 + pi + 2] = make_uint2(hi[2], hi[3]);
            *(uint2*)&su[P_XTLO + p * 36 + pi]     = make_uint2(lo[0], lo[1]);
            *(uint2*)&su[P_XTLO + p * 36 + pi + 2] = make_uint2(lo[2], lo[3]);
        }
    }
    __syncthreads();

    auto mm = [&](uint32_t offA, uint32_t offB, float (*dd)[4]) {
        #pragma unroll
        for (int ks = 0; ks < 4; ks++) {
            int kb = ks * 8;
            uint32_t ah[4], al[4];
            int o0 = (wm * 16 + g) * 36 + kb + t4;
            int o1 = o0 + 8 * 36;
            ah[0] = su[offA + o0];     ah[1] = su[offA + o1];
            ah[2] = su[offA + o0 + 4]; ah[3] = su[offA + o1 + 4];
            al[0] = su[offA + 2304 + o0];     al[1] = su[offA + 2304 + o1];
            al[2] = su[offA + 2304 + o0 + 4]; al[3] = su[offA + 2304 + o1 + 4];
            #pragma unroll
            for (int nt = 0; nt < 4; nt++) {
                int ob = (wn * 32 + nt * 8 + g) * 36 + kb + t4;
                uint32_t bh0 = su[offB + ob], bh1 = su[offB + ob + 4];
                uint32_t bl0 = su[offB + 2304 + ob], bl1 = su[offB + 2304 + ob + 4];
                MMA_BF16(dd[nt], ah, bh0, bh1);
                MMA_BF16(dd[nt], ah, bl0, bl1);
                MMA_BF16(dd[nt], al, bh0, bh1);
            }
        }
    };

    float d[4][4];
    #pragma unroll
    for (int nt = 0; nt < 4; nt++)
        #pragma unroll
        for (int j = 0; j < 4; j++) d[nt][j] = 0.f;
    mm(P_A, P_B, d);

    int t0 = wm * 16 + g, t1 = t0 + 8;
    float ct0 = sf[P_CUM2 + t0], ct1 = sf[P_CUM2 + t1];
    float gv[4][4];
    #pragma unroll
    for (int nt = 0; nt < 4; nt++) {
        int s0 = wn * 32 + nt * 8 + 2 * t4, s1 = s0 + 1;
        float cs0 = sf[P_CUM2 + s0], cs1 = sf[P_CUM2 + s1];
        float w0 = sf[P_DT2 + s0],  w1 = sf[P_DT2 + s1];
        gv[nt][0] = (s0 <= t0) ? d[nt][0] * expf(ct0 - cs0) * w0 : 0.f;
        gv[nt][1] = (s1 <= t0) ? d[nt][1] * expf(ct0 - cs1) * w1 : 0.f;
        gv[nt][2] = (s0 <= t1) ? d[nt][2] * expf(ct1 - cs0) * w0 : 0.f;
        gv[nt][3] = (s1 <= t1) ? d[nt][3] * expf(ct1 - cs1) * w1 : 0.f;
    }
    __syncthreads();

    #pragma unroll
    for (int nt = 0; nt < 4; nt++) {
        int pi = wn * 16 + nt * 4 + t4;
        uint32_t h01 = packbf(gv[nt][0], gv[nt][1]);
        float r0 = gv[nt][0] - __uint_as_float(h01 << 16);
        float r1 = gv[nt][1] - __uint_as_float(h01 & 0xffff0000u);
        su[P_A   + t0 * 36 + pi] = h01;
        su[P_ALO + t0 * 36 + pi] = packbf(r0, r1);
        uint32_t h23 = packbf(gv[nt][2], gv[nt][3]);
        float r2 = gv[nt][2] - __uint_as_float(h23 << 16);
        float r3 = gv[nt][3] - __uint_as_float(h23 & 0xffff0000u);
        su[P_A   + t1 * 36 + pi] = h23;
        su[P_ALO + t1 * 36 + pi] = packbf(r2, r3);
    }
    __syncthreads();

    #pragma unroll
    for (int nt = 0; nt < 4; nt++)
        #pragma unroll
        for (int j = 0; j < 4; j++) d[nt][j] = 0.f;
    mm(P_A, P_XT, d);
    mm(P_C2, P_HT, d);

    float* yo = g_y + ((size_t)b * SEQLEN + c * 64) * DINNER + h * 64;
    #pragma unroll
    for (int nt = 0; nt < 4; nt++) {
        int p0 = wn * 32 + nt * 8 + 2 * t4;
        float2 x0 = *(const float2*)&sf[P_XF + t0 * 68 + p0];
        float2 x1 = *(const float2*)&sf[P_XF + t1 * 68 + p0];
        float2 v0 = make_float2(d[nt][0] + Dh * x0.x, d[nt][1] + Dh * x0.y);
        float2 v1 = make_float2(d[nt][2] + Dh * x1.x, d[nt][3] + Dh * x1.y);
        *(float2*)&yo[(size_t)t0 * DINNER + p0] = v0;
        *(float2*)&yo[(size_t)t1 * DINNER + p0] = v1;
    }
}

// ---------------- 5) gate + RMSNorm (writes bf16 hi/lo planes) --------------
__global__ void __launch_bounds__(256) gate_rms_kernel(const float* __restrict__ norm_w)
{
    __shared__ float sh[8];
    int row = blockIdx.x, tid = threadIdx.x;
    const float4* y4 = (const float4*)(g_y  + (size_t)row * DINNER);
    const float4* z4 = (const float4*)(g_zx + (size_t)row * DINPROJ);
    float4 a0 = y4[tid], a1 = y4[tid + 256];
    float4 z0 = z4[tid], z1 = z4[tid + 256];
    float g[8];
    g[0] = a0.x * (z0.x / (1.f + expf(-z0.x)));
    g[1] = a0.y * (z0.y / (1.f + expf(-z0.y)));
    g[2] = a0.z * (z0.z / (1.f + expf(-z0.z)));
    g[3] = a0.w * (z0.w / (1.f + expf(-z0.w)));
    g[4] = a1.x * (z1.x / (1.f + expf(-z1.x)));
    g[5] = a1.y * (z1.y / (1.f + expf(-z1.y)));
    g[6] = a1.z * (z1.z / (1.f + expf(-z1.z)));
    g[7] = a1.w * (z1.w / (1.f + expf(-z1.w)));
    float ss = 0.f;
    #pragma unroll
    for (int j = 0; j < 8; j++) ss += g[j] * g[j];
    float tot = block_sum256(ss, sh);
    float inv = rsqrtf(tot * (1.f / DINNER) + 1e-5f);
    float4 w0 = ((const float4*)norm_w)[tid];
    float4 w1 = ((const float4*)norm_w)[tid + 256];
    float4 o0, o1;
    o0.x = g[0] * inv * w0.x; o0.y = g[1] * inv * w0.y;
    o0.z = g[2] * inv * w0.z; o0.w = g[3] * inv * w0.w;
    o1.x = g[4] * inv * w1.x; o1.y = g[5] * inv * w1.y;
    o1.z = g[6] * inv * w1.z; o1.w = g[7] * inv * w1.w;
    uint2 hi, lo;
    size_t idx = (size_t)row * DINNER + tid * 4;
    split4(o0, hi, lo);
    *(uint2*)(g_ynh + idx) = hi;
    *(uint2*)(g_ynl + idx) = lo;
    split4(o1, hi, lo);
    *(uint2*)(g_ynh + idx + 1024) = hi;
    *(uint2*)(g_ynl + idx + 1024) = lo;
}

// ---------------- launcher -------------------------------------------------
extern "C" void kernel_launch(void* const* d_in, const int* in_sizes, int n_in,
                              void* d_out, int out_size)
{
    const float* x       = (const float*)d_in[0];
    const float* ln_w    = (const float*)d_in[1];
    const float* ln_b    = (const float*)d_in[2];
    const float* W_in    = (const float*)d_in[3];
    const float* conv_w  = (const float*)d_in[4];
    const float* conv_b  = (const float*)d_in[5];
    const float* dt_bias = (const float*)d_in[6];
    const float* A_log   = (const float*)d_in[7];
    const float* Dp      = (const float*)d_in[8];
    const float* norm_w  = (const float*)d_in[9];
    const float* W_out   = (const float*)d_in[10];
    float* out = (float*)d_out;

    cudaFuncSetAttribute(gemm_tc<DINPROJ, DMODEL, false>,
                         cudaFuncAttributeMaxDynamicSharedMemorySize, SMEM_DYN);
    cudaFuncSetAttribute(gemm_tc<DMODEL, DINNER, true>,
                         cudaFuncAttributeMaxDynamicSharedMemorySize, SMEM_DYN);
    cudaFuncSetAttribute(s1_kernel,
                         cudaFuncAttributeMaxDynamicSharedMemorySize, S1_SMEMB);
    cudaFuncSetAttribute(s2_kernel,
                         cudaFuncAttributeMaxDynamicSharedMemorySize, S2N_B);

    uint16_t *wih, *wil, *woh, *wol;
    cudaGetSymbolAddress((void**)&wih, g_wih);
    cudaGetSymbolAddress((void**)&wil, g_wil);
    cudaGetSymbolAddress((void**)&woh, g_woh);
    cudaGetSymbolAddress((void**)&wol, g_wol);

    wsplit_kernel<<<(DINPROJ * DMODEL / 4 + 255) / 256, 256>>>(W_in, wih, wil,
                                                               DINPROJ * DMODEL / 4); // 1
    wsplit_kernel<<<(DMODEL * DINNER / 4 + 255) / 256, 256>>>(W_out, woh, wol,
                                                              DMODEL * DINNER / 4);   // 2

    ln_kernel<<<BL, 256>>>(x, ln_w, ln_b);                          // 3

    gemm_tc<DINPROJ, DMODEL, false>                                 // 4 <- ncu window
        <<<dim3((DINPROJ + 127) / 128, BL / 128), 256, SMEM_DYN>>>(nullptr, nullptr);

    conv_dt_kernel<<<dim3(9, BL), 256>>>(conv_w, conv_b, dt_bias);  // 5

    s1_kernel<<<BATCH * NHEADS * 2, 256, S1_SMEMB>>>(A_log);        // 6

    s2_kernel<<<BATCH * NHEADS * NCHUNK, 256, S2N_B>>>(A_log, Dp);  // 7

    gate_rms_kernel<<<BL, 256>>>(norm_w);                           // 8

    gemm_tc<DMODEL, DINNER, true>                                   // 9
        <<<dim3(DMODEL / 128, BL / 128), 256, SMEM_DYN>>>(x, out);
}

// round 14
// speedup vs baseline: 1.0213x; 1.0213x over previous
#include <cuda_runtime.h>
#include <cstdint>
#include <math.h>

#define BATCH   2
#define SEQLEN  4096
#define DMODEL  1024
#define DINNER  2048
#define NHEADS  32
#define HEADDIM 64
#define DSTATE  64
#define CONVDIM 2176            // DINNER + 2*DSTATE
#define DINPROJ 4256            // 2*DINNER + 2*DSTATE + NHEADS
#define BL      8192            // BATCH*SEQLEN
#define CHUNK   64
#define NCHUNK  (SEQLEN / CHUNK)   // 64

// ---------------- scratch (static device globals: no allocations) ----------
__device__ float    g_zx  [(size_t)BL * DINPROJ];
__device__ float    g_xbca[(size_t)BL * CONVDIM];
__device__ float    g_dt  [(size_t)BL * NHEADS];
__device__ float    g_y   [(size_t)BL * DINNER];
// pre-split bf16 hi/lo operand planes
__device__ uint16_t g_uh  [(size_t)BL * DMODEL];
__device__ uint16_t g_ul  [(size_t)BL * DMODEL];
__device__ uint16_t g_ynh [(size_t)BL * DINNER];
__device__ uint16_t g_ynl [(size_t)BL * DINNER];
__device__ uint16_t g_wih [(size_t)DINPROJ * DMODEL];
__device__ uint16_t g_wil [(size_t)DINPROJ * DMODEL];
__device__ uint16_t g_woh [(size_t)DMODEL * DINNER];
__device__ uint16_t g_wol [(size_t)DMODEL * DINNER];
// scan pre-split planes
__device__ uint16_t g_bcsh[(size_t)BL * 128];                       // [t][B64|C64] hi
__device__ uint16_t g_bcsl[(size_t)BL * 128];
__device__ uint16_t g_bth [(size_t)BATCH * NCHUNK * 64 * 64];       // B^T [bc][n][t] hi
__device__ uint16_t g_btl [(size_t)BATCH * NCHUNK * 64 * 64];
__device__ uint16_t g_hch [(size_t)BATCH * NHEADS * NCHUNK * 4096]; // carry [p][n] hi
__device__ uint16_t g_hcl [(size_t)BATCH * NHEADS * NCHUNK * 4096];

// ---------------- helpers ---------------------------------------------------
__device__ __forceinline__ uint32_t smem_u32(const void* p) {
    uint32_t a;
    asm("{ .reg .u64 t; cvta.to.shared.u64 t, %1; cvt.u32.u64 %0, t; }"
        : "=r"(a) : "l"(p));
    return a;
}
// pack two f32 -> bf16x2 (first arg in LOW half)
__device__ __forceinline__ uint32_t packbf(float lo, float hi) {
    uint32_t r;
    asm("cvt.rn.bf16x2.f32 %0, %1, %2;" : "=r"(r) : "f"(hi), "f"(lo));
    return r;
}
// split float4 -> hi uint2 / lo uint2 (bf16x2 pairs)
__device__ __forceinline__ void split4(float4 v, uint2& hi, uint2& lo) {
    uint32_t h01 = packbf(v.x, v.y);
    uint32_t h23 = packbf(v.z, v.w);
    float rx = v.x - __uint_as_float(h01 << 16);
    float ry = v.y - __uint_as_float(h01 & 0xffff0000u);
    float rz = v.z - __uint_as_float(h23 << 16);
    float rw = v.w - __uint_as_float(h23 & 0xffff0000u);
    hi = make_uint2(h01, h23);
    lo = make_uint2(packbf(rx, ry), packbf(rz, rw));
}
__device__ __forceinline__ void split2(float a, float b, uint32_t& hi, uint32_t& lo) {
    hi = packbf(a, b);
    float ra = a - __uint_as_float(hi << 16);
    float rb = b - __uint_as_float(hi & 0xffff0000u);
    lo = packbf(ra, rb);
}

#define MMA_BF16(d, a, b0, b1) \
    asm volatile("mma.sync.aligned.m16n8k16.row.col.f32.bf16.bf16.f32 " \
        "{%0,%1,%2,%3}, {%4,%5,%6,%7}, {%8,%9}, {%0,%1,%2,%3};" \
        : "+f"((d)[0]), "+f"((d)[1]), "+f"((d)[2]), "+f"((d)[3]) \
        : "r"((a)[0]), "r"((a)[1]), "r"((a)[2]), "r"((a)[3]), \
          "r"(b0), "r"(b1))

#define LDSM_X4(r, addr) \
    asm volatile("ldmatrix.sync.aligned.m8n8.x4.shared.b16 {%0,%1,%2,%3}, [%4];" \
        : "=r"((r)[0]), "=r"((r)[1]), "=r"((r)[2]), "=r"((r)[3]) : "r"(addr))

#define CP_ASYNC16(dst, src) \
    asm volatile("cp.async.ca.shared.global [%0], [%1], 16;" \
        :: "r"(dst), "l"(src) : "memory")
#define CP_ASYNC16_P(dst, src, nbytes) \
    asm volatile("cp.async.ca.shared.global [%0], [%1], 16, %2;" \
        :: "r"(dst), "l"(src), "r"(nbytes) : "memory")
#define CP_ASYNC4(dst, src) \
    asm volatile("cp.async.ca.shared.global [%0], [%1], 4;" \
        :: "r"(dst), "l"(src) : "memory")
#define CP_COMMIT() asm volatile("cp.async.commit_group;" ::: "memory")
#define CP_WAIT0()  asm volatile("cp.async.wait_group 0;" ::: "memory")
#define CP_WAIT1()  asm volatile("cp.async.wait_group 1;" ::: "memory")

// -------- weight split kernel: fp32 -> bf16 hi/lo ---------------------------
__global__ void __launch_bounds__(256) wsplit_kernel(const float* __restrict__ src,
                                                     uint16_t* __restrict__ dh,
                                                     uint16_t* __restrict__ dl,
                                                     int n4)
{
    int i = blockIdx.x * 256 + threadIdx.x;
    if (i < n4) {
        float4 v = ((const float4*)src)[i];
        uint2 hi, lo;
        split4(v, hi, lo);
        ((uint2*)dh)[i] = hi;
        ((uint2*)dl)[i] = lo;
    }
}

// =============== bf16x3 emulated-fp32 NT GEMM (cp.async + LDSM) ============
#define KT        32
#define RSU       20                       // row stride (uint32 pairs, 80 B)
#define PL_AHI    0
#define PL_ALO    2560
#define PL_BHI    5120
#define PL_BLO    7680
#define STAGE_U   10240                    // uint32 per stage
#define SMEM_DYN  (2 * STAGE_U * 4)        // 81920 bytes

template<int N, int K, bool SECOND>
__global__ void __launch_bounds__(256, 2) gemm_tc(const float* __restrict__ resid,
                                                  float* __restrict__ outp)
{
    extern __shared__ uint32_t smu[];
    const uint16_t* __restrict__ Ah = SECOND ? g_ynh : g_uh;
    const uint16_t* __restrict__ Al = SECOND ? g_ynl : g_ul;
    const uint16_t* __restrict__ Wh = SECOND ? g_woh : g_wih;
    const uint16_t* __restrict__ Wl = SECOND ? g_wol : g_wil;
    float* __restrict__ Cptr        = SECOND ? outp : g_zx;

    int tid = threadIdx.x;
    int wid = tid >> 5, lane = tid & 31;
    int bm = blockIdx.y, bn = blockIdx.x;

    uint32_t sb = smem_u32(smu);

    int rA = tid >> 2, cA = (tid & 3) * 16;       // row 0..63, byte chunk
    const int NKT = K / KT;
    auto issue = [&](int kt) {
        if (kt < NKT) {
            uint32_t dst = sb + (uint32_t)(kt & 1) * (STAGE_U * 4);
            #pragma unroll
            for (int i = 0; i < 2; i++) {
                int row = rA + i * 64;
                uint32_t so = (uint32_t)(row * (RSU * 4)) + cA;
                size_t ao = (size_t)(bm * 128 + row) * K + kt * KT + (cA >> 1);
                CP_ASYNC16(dst + PL_AHI * 4 + so, Ah + ao);
                CP_ASYNC16(dst + PL_ALO * 4 + so, Al + ao);
                int nrow = bn * 128 + row;
                int nb = (nrow < N) ? 16 : 0;
                size_t bo = (size_t)nrow * K + kt * KT + (cA >> 1);
                CP_ASYNC16_P(dst + PL_BHI * 4 + so, Wh + bo, nb);
                CP_ASYNC16_P(dst + PL_BLO * 4 + so, Wl + bo, nb);
            }
        }
        CP_COMMIT();
    };

    int wm = wid >> 1, wn = wid & 1;
    int g = lane >> 2, t4 = lane & 3;

    uint32_t aoff = (uint32_t)(((wm * 32 + (lane & 15)) * RSU + 4 * (lane >> 4)) * 4);
    uint32_t boff = (uint32_t)(((wn * 64 + 8 * (lane >> 4) + (lane & 7)) * RSU
                                + 4 * ((lane >> 3) & 1)) * 4);

    float d[2][8][4];
    #pragma unroll
    for (int mt = 0; mt < 2; mt++)
        #pragma unroll
        for (int nt = 0; nt < 8; nt++)
            #pragma unroll
            for (int j = 0; j < 4; j++) d[mt][nt][j] = 0.f;

    issue(0);

    #pragma unroll 1
    for (int kt = 0; kt < NKT; ++kt) {
        issue(kt + 1);
        if (kt + 1 < NKT) CP_WAIT1(); else CP_WAIT0();
        __syncthreads();

        uint32_t base = sb + (uint32_t)(kt & 1) * (STAGE_U * 4);
        #pragma unroll
        for (int ks = 0; ks < 2; ks++) {
            uint32_t kby = (uint32_t)(ks * 8 * 4);
            uint32_t ah[2][4], al[2][4];
            #pragma unroll
            for (int mt = 0; mt < 2; mt++) {
                uint32_t aa = base + aoff + (uint32_t)(mt * 16 * RSU * 4) + kby;
                LDSM_X4(ah[mt], aa + PL_AHI * 4);
                LDSM_X4(al[mt], aa + PL_ALO * 4);
            }
            #pragma unroll
            for (int ntp = 0; ntp < 4; ntp++) {
                uint32_t ba = base + boff + (uint32_t)(ntp * 16 * RSU * 4) + kby;
                uint32_t bh[4], bl[4];
                LDSM_X4(bh, ba + PL_BHI * 4);
                LDSM_X4(bl, ba + PL_BLO * 4);
                #pragma unroll
                for (int mt = 0; mt < 2; mt++) {
                    MMA_BF16(d[mt][2*ntp],   ah[mt], bh[0], bh[1]);
                    MMA_BF16(d[mt][2*ntp],   ah[mt], bl[0], bl[1]);
                    MMA_BF16(d[mt][2*ntp],   al[mt], bh[0], bh[1]);
                    MMA_BF16(d[mt][2*ntp+1], ah[mt], bh[2], bh[3]);
                    MMA_BF16(d[mt][2*ntp+1], ah[mt], bl[2], bl[3]);
                    MMA_BF16(d[mt][2*ntp+1], al[mt], bh[2], bh[3]);
                }
            }
        }
        __syncthreads();
    }

    #pragma unroll
    for (int mt = 0; mt < 2; mt++) {
        int row = bm * 128 + wm * 32 + mt * 16 + g;
        #pragma unroll
        for (int nt = 0; nt < 8; nt++) {
            int col = bn * 128 + wn * 64 + nt * 8 + t4 * 2;
            if (col < N) {
                size_t i0 = (size_t)row * N + col;
                size_t i1 = (size_t)(row + 8) * N + col;
                float2 v0 = make_float2(d[mt][nt][0], d[mt][nt][1]);
                float2 v1 = make_float2(d[mt][nt][2], d[mt][nt][3]);
                if (SECOND) {
                    float2 r0v = *(const float2*)(resid + i0);
                    float2 r1v = *(const float2*)(resid + i1);
                    v0.x += r0v.x; v0.y += r0v.y;
                    v1.x += r1v.x; v1.y += r1v.y;
                }
                *(float2*)(Cptr + i0) = v0;
                *(float2*)(Cptr + i1) = v1;
            }
        }
    }
}

// ---------------- block reduction helper -----------------------------------
__device__ __forceinline__ float block_sum256(float v, float* sh) {
    #pragma unroll
    for (int o = 16; o; o >>= 1) v += __shfl_xor_sync(0xffffffffu, v, o);
    int lane = threadIdx.x & 31, wid = threadIdx.x >> 5;
    __syncthreads();
    if (lane == 0) sh[wid] = v;
    __syncthreads();
    float tt = 0.f;
    #pragma unroll
    for (int j = 0; j < 8; j++) tt += sh[j];
    return tt;
}

// ---------------- 1) LayerNorm (writes bf16 hi/lo planes) -------------------
__global__ void __launch_bounds__(256) ln_kernel(const float* __restrict__ x,
                                                 const float* __restrict__ w,
                                                 const float* __restrict__ bparm)
{
    __shared__ float sh[8];
    int row = blockIdx.x, tid = threadIdx.x;
    const float4* xr = (const float4*)(x + (size_t)row * DMODEL);
    float4 v = xr[tid];
    float s  = v.x + v.y + v.z + v.w;
    float mu = block_sum256(s, sh) * (1.f / DMODEL);
    float d0 = v.x - mu, d1 = v.y - mu, d2 = v.z - mu, d3 = v.w - mu;
    float vs = d0*d0 + d1*d1 + d2*d2 + d3*d3;
    float var = block_sum256(vs, sh) * (1.f / DMODEL);
    float inv = rsqrtf(var + 1e-5f);
    float4 wv = ((const float4*)w)[tid];
    float4 bv = ((const float4*)bparm)[tid];
    float4 o;
    o.x = d0 * inv * wv.x + bv.x;
    o.y = d1 * inv * wv.y + bv.y;
    o.z = d2 * inv * wv.z + bv.z;
    o.w = d3 * inv * wv.w + bv.w;
    uint2 hi, lo;
    split4(o, hi, lo);
    size_t idx = (size_t)row * DMODEL + tid * 4;
    *(uint2*)(g_uh + idx) = hi;
    *(uint2*)(g_ul + idx) = lo;
}

// ---------------- 3) causal conv(4)+SiLU, fused softplus(dt) ---------------
__global__ void __launch_bounds__(256) conv_dt_kernel(const float* __restrict__ conv_w,
                                                      const float* __restrict__ conv_b,
                                                      const float* __restrict__ dt_bias)
{
    int i = blockIdx.y;
    int c = blockIdx.x * 256 + threadIdx.x;
    int b = i >> 12;
    int l = i & 4095;
    if (c < CONVDIM) {
        float w0 = conv_w[c*4+0], w1 = conv_w[c*4+1];
        float w2 = conv_w[c*4+2], w3 = conv_w[c*4+3];
        const float* col = g_zx + (size_t)(b << 12) * DINPROJ + DINNER + c;
        float s = conv_b[c];
        if (l >= 3) s += col[(size_t)(l-3) * DINPROJ] * w0;
        if (l >= 2) s += col[(size_t)(l-2) * DINPROJ] * w1;
        if (l >= 1) s += col[(size_t)(l-1) * DINPROJ] * w2;
        s += col[(size_t)l * DINPROJ] * w3;
        s = s / (1.f + expf(-s));
        g_xbca[(size_t)i * CONVDIM + c] = s;
    } else if (c < CONVDIM + NHEADS) {
        int hh = c - CONVDIM;
        float v = g_zx[(size_t)i * DINPROJ + (DINNER + CONVDIM) + hh] + dt_bias[hh];
        g_dt[(size_t)i * NHEADS + hh] = (v > 20.f) ? v : log1pf(expf(v));
    }
}

// ---------------- 3b) BC split: straight [t][128] + transposed B [n][t] -----
__global__ void __launch_bounds__(256) bcsplit_kernel()
{
    __shared__ float sb[64][132];
    int bc = blockIdx.x;                  // b*NCHUNK + chunk (rows bc*64..+63)
    int tid = threadIdx.x;
    const float* src = g_xbca + (size_t)bc * 64 * CONVDIM + 2048;
    #pragma unroll
    for (int i = 0; i < 8; i++) {
        int idx = tid + i * 256;          // 2048 float4
        int t = idx >> 5, c4 = (idx & 31) * 4;
        float4 v = *(const float4*)(src + (size_t)t * CONVDIM + c4);
        uint2 hi, lo;
        split4(v, hi, lo);
        size_t o = ((size_t)(bc * 64 + t)) * 128 + c4;
        *(uint2*)(g_bcsh + o) = hi;
        *(uint2*)(g_bcsl + o) = lo;
        *(float4*)&sb[t][c4] = v;
    }
    __syncthreads();
    // transposed B (cols 0..63 of BC region): output row n, 64 t values
    int n = tid >> 2, tg = (tid & 3) * 16;
    uint32_t hi[8], lo[8];
    #pragma unroll
    for (int j = 0; j < 8; j++)
        split2(sb[tg + 2*j][n], sb[tg + 2*j + 1][n], hi[j], lo[j]);
    size_t o = ((size_t)bc * 64 + n) * 64 + tg;
    *(uint4*)(g_bth + o)     = make_uint4(hi[0], hi[1], hi[2], hi[3]);
    *(uint4*)(g_bth + o + 8) = make_uint4(hi[4], hi[5], hi[6], hi[7]);
    *(uint4*)(g_btl + o)     = make_uint4(lo[0], lo[1], lo[2], lo[3]);
    *(uint4*)(g_btl + o + 8) = make_uint4(lo[4], lo[5], lo[6], lo[7]);
}

// -------- warp-0 inclusive scan of 64 s-values (dt*Ah) -> cum[64] ----------
__device__ __forceinline__ void scan64(const float* dtv, float Ah, float* cum, int tid) {
    if (tid < 32) {
        float a = dtv[tid] * Ah;
        float b = dtv[32 + tid] * Ah;
        #pragma unroll
        for (int o = 1; o < 32; o <<= 1) {
            float ta = __shfl_up_sync(0xffffffffu, a, o);
            float tb = __shfl_up_sync(0xffffffffu, b, o);
            if (tid >= o) { a += ta; b += tb; }
        }
        float totA = __shfl_sync(0xffffffffu, a, 31);
        cum[tid]      = a;
        cum[32 + tid] = totA + b;
    }
}

// ---------------- 4a) S1: chunk-state pass (bf16x3 MMA, pre-split B^T) -----
// grid 128: b, h, nh. h[n][p] += sum_t B[t][n] * (w_t X[t][p]).
// A-op = B^T planes (cp.async from g_bth/l). B-op = XWT planes built per chunk.
// Carries stored pre-split bf16 [p][n] for S2.
#define S1_XF    0                          // fp32 X [64][68]
#define S1_BT    4352                       // B^T hi [32 n][36] u32
#define S1_BTLO  5504
#define S1_DT    6656
#define S1_BUF   6720                       // ring buffer (x2)
#define S1_XWT   13440                      // XWT hi [64 p][36] u32
#define S1_XWTLO 15744
#define S1_W     18048
#define S1_CUM   18112
#define S1_SMEMF 18176
#define S1_SMEMB (S1_SMEMF * 4)             // 72704 bytes

__global__ void __launch_bounds__(256) s1_kernel(const float* __restrict__ A_log)
{
    extern __shared__ float sm[];
    uint32_t* su = (uint32_t*)sm;
    int bx = blockIdx.x;
    int b = bx >> 6, h = (bx >> 1) & 31, nh = bx & 1;
    int tid = threadIdx.x;
    int wid = tid >> 5, lane = tid & 31;
    int wm = wid & 1, wn = wid >> 1;        // n-tile (16), p-quarter (16)
    int g = lane >> 2, t4 = lane & 3;
    float Ah = -expf(A_log[h]);

    float* w   = sm + S1_W;
    float* cum = sm + S1_CUM;
    uint32_t sbase = smem_u32(sm);

    const float* base = g_xbca + (size_t)b * SEQLEN * CONVDIM;
    const float* dtb  = g_dt   + (size_t)b * SEQLEN * NHEADS + h;

    auto issue = [&](int c) {
        if (c < NCHUNK) {
            uint32_t dst = sbase + (uint32_t)(c & 1) * (S1_BUF * 4);
            const float* rowb = base + (size_t)c * CHUNK * CONVDIM;
            #pragma unroll
            for (int i = 0; i < 4; i++) {              // X fp32: 1024 f4
                int f4 = tid + i * 256;
                int t = f4 >> 4, j = (f4 & 15) * 4;
                CP_ASYNC16(dst + (uint32_t)(t * 68 + j) * 4,
                           rowb + (size_t)t * CONVDIM + h * 64 + j);
            }
            {                                          // B^T planes
                int n = tid >> 3, ch = tid & 7;
                size_t src = ((size_t)(b * NCHUNK + c) * 64 + nh * 32 + n) * 64 + ch * 8;
                uint32_t so = (uint32_t)(n * 36 + ch * 4) * 4;
                CP_ASYNC16(dst + S1_BT * 4 + so, g_bth + src);
                CP_ASYNC16(dst + S1_BTLO * 4 + so, g_btl + src);
            }
            if (tid < 64)
                CP_ASYNC4(dst + S1_DT * 4 + tid * 4,
                          dtb + (size_t)(c * CHUNK + tid) * NHEADS);
        }
        CP_COMMIT();
    };

    float d0[4] = {0.f, 0.f, 0.f, 0.f};
    float d1[4] = {0.f, 0.f, 0.f, 0.f};

    issue(0); issue(1);

    for (int c = 0; c < NCHUNK; c++) {
        CP_WAIT1();
        __syncthreads();
        float* S = sm + (c & 1) * S1_BUF;
        uint32_t* SU = su + (c & 1) * S1_BUF;

        scan64(S + S1_DT, Ah, cum, tid);
        __syncthreads();

        float cl = cum[63];
        float E  = expf(cl);
        if (tid < 64) w[tid] = expf(cl - cum[tid]) * S[S1_DT + tid];

        // carry store (state at chunk start) as bf16 hi/lo planes [p][n]
        {
            size_t hcb = (((size_t)(b * 32 + h)) * NCHUNK + c) * 4096;
            int n0 = nh * 32 + wm * 16 + g;
            int p0 = wn * 16 + 2 * t4;
            auto stbf = [&](int p, int n, float v) {
                uint32_t hb = packbf(v, v);
                float l = v - __uint_as_float(hb << 16);
                uint32_t lb = packbf(l, l);
                size_t a = hcb + (size_t)p * 64 + n;
                g_hch[a] = (uint16_t)hb;
                g_hcl[a] = (uint16_t)lb;
            };
            stbf(p0,     n0,     d0[0]); stbf(p0 + 1, n0,     d0[1]);
            stbf(p0,     n0 + 8, d0[2]); stbf(p0 + 1, n0 + 8, d0[3]);
            stbf(p0 + 8, n0,     d1[0]); stbf(p0 + 9, n0,     d1[1]);
            stbf(p0 + 8, n0 + 8, d1[2]); stbf(p0 + 9, n0 + 8, d1[3]);
        }
        #pragma unroll
        for (int j = 0; j < 4; j++) { d0[j] *= E; d1[j] *= E; }
        __syncthreads();                      // w ready; prev XWT reads done

        // build XWT planes: [p][t-pairs], value = w_t * X[t][p]
        {
            int p = tid & 63, tq = tid >> 6;
            uint32_t hi[8], lo[8];
            #pragma unroll
            for (int q = 0; q < 8; q++) {
                int t0 = tq * 16 + 2 * q;
                float a = S[t0 * 68 + p] * w[t0];
                float bb = S[(t0 + 1) * 68 + p] * w[t0 + 1];
                split2(a, bb, hi[q], lo[q]);
            }
            int o = S1_XWT + p * 36 + tq * 8;
            *(uint4*)&su[o]            = make_uint4(hi[0], hi[1], hi[2], hi[3]);
            *(uint4*)&su[o + 4]        = make_uint4(hi[4], hi[5], hi[6], hi[7]);
            *(uint4*)&su[o + 2304]     = make_uint4(lo[0], lo[1], lo[2], lo[3]);
            *(uint4*)&su[o + 2304 + 4] = make_uint4(lo[4], lo[5], lo[6], lo[7]);
        }
        __syncthreads();                      // XWT ready

        // MMA: dd[pb] += B^T(n,t) x XWT(p,t)^T
        const uint32_t* BT = SU + S1_BT;
        #pragma unroll
        for (int kc = 0; kc < 4; kc++) {
            int o0 = (wm * 16 + g) * 36 + kc * 8 + t4;
            int o1 = o0 + 8 * 36;
            uint32_t ah[4], al[4];
            ah[0] = BT[o0];     ah[1] = BT[o1];
            ah[2] = BT[o0 + 4]; ah[3] = BT[o1 + 4];
            al[0] = BT[1152 + o0];     al[1] = BT[1152 + o1];
            al[2] = BT[1152 + o0 + 4]; al[3] = BT[1152 + o1 + 4];
            #pragma unroll
            for (int pb = 0; pb < 2; pb++) {
                int pr = S1_XWT + (wn * 16 + pb * 8 + g) * 36 + kc * 8 + t4;
                uint32_t bh0 = su[pr], bh1 = su[pr + 4];
                uint32_t bl0 = su[pr + 2304], bl1 = su[pr + 2304 + 4];
                float* dd = pb ? d1 : d0;
                MMA_BF16(dd, ah, bh0, bh1);
                MMA_BF16(dd, ah, bl0, bl1);
                MMA_BF16(dd, al, bh0, bh1);
            }
        }
        __syncthreads();                      // reads done before restage
        issue(c + 2);
    }
}

// ---------------- 4b) S2: per-chunk parallel y (bf16x3 MMA, pre-split) ------
#define P_A     0          // C hi (later G hi)
#define P_ALO   2304
#define P_B     4608
#define P_BLO   6912
#define P_C2    9216
#define P_C2LO  11520
#define P_XT    13824
#define P_XTLO  16128
#define P_HT    18432
#define P_HTLO  20736
#define P_XF    23040      // fp32 X tile [64][68]
#define P_DT2   27392
#define P_CUM2  27456
#define S2N_U   27520
#define S2N_B   (S2N_U * 4)   // 110080 bytes

__global__ void __launch_bounds__(256) s2_kernel(const float* __restrict__ A_log,
                                                 const float* __restrict__ Dp)
{
    extern __shared__ uint32_t su[];
    float* sf = (float*)su;
    int bx = blockIdx.x;
    int c = bx & 63, h = (bx >> 6) & 31, b = bx >> 11;
    int tid = threadIdx.x;
    int wid = tid >> 5, lane = tid & 31;
    int wm = wid >> 1, wn = wid & 1;        // 4x2 warp grid, warp tile 16x32
    int g = lane >> 2, t4 = lane & 3;
    float Ah = -expf(A_log[h]);
    float Dh = Dp[h];

    uint32_t sb = smem_u32(su);
    const float* rowb = g_xbca + ((size_t)b * SEQLEN + c * 64) * CONVDIM;

    // ---- async loads: C/B planes, HT planes, X fp32, dt --------------------
    {
        int r = tid >> 2, q = tid & 3;
        size_t ib = ((size_t)(b * SEQLEN + c * 64 + r)) * 128;
        size_t hb = (((size_t)(b * 32 + h)) * NCHUNK + c) * 4096 + (size_t)r * 64;
        #pragma unroll
        for (int k = 0; k < 2; k++) {
            int ch = q * 2 + k;
            uint32_t so = (uint32_t)(r * 36 + ch * 4) * 4;
            CP_ASYNC16(sb + P_A * 4 + so,    g_bcsh + ib + 64 + ch * 8);
            CP_ASYNC16(sb + P_ALO * 4 + so,  g_bcsl + ib + 64 + ch * 8);
            CP_ASYNC16(sb + P_B * 4 + so,    g_bcsh + ib + ch * 8);
            CP_ASYNC16(sb + P_BLO * 4 + so,  g_bcsl + ib + ch * 8);
            CP_ASYNC16(sb + P_HT * 4 + so,   g_hch + hb + ch * 8);
            CP_ASYNC16(sb + P_HTLO * 4 + so, g_hcl + hb + ch * 8);
        }
        #pragma unroll
        for (int i = 0; i < 4; i++) {
            int f4 = tid + i * 256;
            int t = f4 >> 4, j = (f4 & 15) * 4;
            CP_ASYNC16(sb + (uint32_t)(P_XF + t * 68 + j) * 4,
                       rowb + (size_t)t * CONVDIM + h * 64 + j);
        }
        if (tid < 64)
            CP_ASYNC4(sb + (uint32_t)(P_DT2 + tid) * 4,
                      g_dt + ((size_t)b * SEQLEN + c * 64 + tid) * NHEADS + h);
        CP_COMMIT();
    }

    // fp32 C rows for C2 (independent regular loads)
    int r = tid >> 2;
    int cg = (tid & 3) * 16;
    float4 cre[4];
    #pragma unroll
    for (int i = 0; i < 4; i++)
        cre[i] = *(const float4*)(rowb + (size_t)r * CONVDIM + 2112 + cg + 4 * i);

    CP_WAIT0();
    __syncthreads();

    scan64(sf + P_DT2, Ah, sf + P_CUM2, tid);
    __syncthreads();

    // ---- C2 = Et*C planes, XT planes ---------------------------------------
    {
        float Et = expf(sf[P_CUM2 + r]);
        #pragma unroll
        for (int i = 0; i < 4; i++) {
            float4 v = cre[i];
            v.x *= Et; v.y *= Et; v.z *= Et; v.w *= Et;
            uint2 hi, lo;
            split4(v, hi, lo);
            int col = cg + 4 * i;
            *(uint2*)&su[P_C2 + r * 36 + col / 2]          = hi;
            *(uint2*)&su[P_C2 + 2304 + r * 36 + col / 2]   = lo;
        }
    }
    {
        int p = tid & 63, tq = tid >> 6;
        uint32_t hi[8], lo[8];
        #pragma unroll
        for (int q = 0; q < 8; q++) {
            int t0 = tq * 16 + 2 * q;
            split2(sf[P_XF + t0 * 68 + p], sf[P_XF + (t0 + 1) * 68 + p], hi[q], lo[q]);
        }
        int o = P_XT + p * 36 + tq * 8;
        *(uint4*)&su[o]            = make_uint4(hi[0], hi[1], hi[2], hi[3]);
        *(uint4*)&su[o + 4]        = make_uint4(hi[4], hi[5], hi[6], hi[7]);
        *(uint4*)&su[o + 2304]     = make_uint4(lo[0], lo[1], lo[2], lo[3]);
        *(uint4*)&su[o + 2304 + 4] = make_uint4(lo[4], lo[5], lo[6], lo[7]);
    }
    __syncthreads();

    auto mm = [&](uint32_t offA, uint32_t offB, float (*dd)[4]) {
        #pragma unroll
        for (int ks = 0; ks < 4; ks++) {
            int kb = ks * 8;
            uint32_t ah[4], al[4];
            int o0 = (wm * 16 + g) * 36 + kb + t4;
            int o1 = o0 + 8 * 36;
            ah[0] = su[offA + o0];     ah[1] = su[offA + o1];
            ah[2] = su[offA + o0 + 4]; ah[3] = su[offA + o1 + 4];
            al[0] = su[offA + 2304 + o0];     al[1] = su[offA + 2304 + o1];
            al[2] = su[offA + 2304 + o0 + 4]; al[3] = su[offA + 2304 + o1 + 4];
            #pragma unroll
            for (int nt = 0; nt < 4; nt++) {
                int ob = (wn * 32 + nt * 8 + g) * 36 + kb + t4;
                uint32_t bh0 = su[offB + ob], bh1 = su[offB + ob + 4];
                uint32_t bl0 = su[offB + 2304 + ob], bl1 = su[offB + 2304 + ob + 4];
                MMA_BF16(dd[nt], ah, bh0, bh1);
                MMA_BF16(dd[nt], ah, bl0, bl1);
                MMA_BF16(dd[nt], al, bh0, bh1);
            }
        }
    };

    float d[4][4];
    #pragma unroll
    for (int nt = 0; nt < 4; nt++)
        #pragma unroll
        for (int j = 0; j < 4; j++) d[nt][j] = 0.f;
    mm(P_A, P_B, d);

    int t0 = wm * 16 + g, t1 = t0 + 8;
    float ct0 = sf[P_CUM2 + t0], ct1 = sf[P_CUM2 + t1];
    float gv[4][4];
    #pragma unroll
    for (int nt = 0; nt < 4; nt++) {
        int s0 = wn * 32 + nt * 8 + 2 * t4, s1 = s0 + 1;
        float cs0 = sf[P_CUM2 + s0], cs1 = sf[P_CUM2 + s1];
        float w0 = sf[P_DT2 + s0],  w1 = sf[P_DT2 + s1];
        gv[nt][0] = (s0 <= t0) ? d[nt][0] * expf(ct0 - cs0) * w0 : 0.f;
        gv[nt][1] = (s1 <= t0) ? d[nt][1] * expf(ct0 - cs1) * w1 : 0.f;
        gv[nt][2] = (s0 <= t1) ? d[nt][2] * expf(ct1 - cs0) * w0 : 0.f;
        gv[nt][3] = (s1 <= t1) ? d[nt][3] * expf(ct1 - cs1) * w1 : 0.f;
    }
    __syncthreads();

    #pragma unroll
    for (int nt = 0; nt < 4; nt++) {
        int pi = wn * 16 + nt * 4 + t4;
        uint32_t h01, l01, h23, l23;
        split2(gv[nt][0], gv[nt][1], h01, l01);
        split2(gv[nt][2], gv[nt][3], h23, l23);
        su[P_A   + t0 * 36 + pi] = h01;
        su[P_ALO + t0 * 36 + pi] = l01;
        su[P_A   + t1 * 36 + pi] = h23;
        su[P_ALO + t1 * 36 + pi] = l23;
    }
    __syncthreads();

    #pragma unroll
    for (int nt = 0; nt < 4; nt++)
        #pragma unroll
        for (int j = 0; j < 4; j++) d[nt][j] = 0.f;
    mm(P_A, P_XT, d);
    mm(P_C2, P_HT, d);

    float* yo = g_y + ((size_t)b * SEQLEN + c * 64) * DINNER + h * 64;
    #pragma unroll
    for (int nt = 0; nt < 4; nt++) {
        int p0 = wn * 32 + nt * 8 + 2 * t4;
        float2 x0 = *(const float2*)&sf[P_XF + t0 * 68 + p0];
        float2 x1 = *(const float2*)&sf[P_XF + t1 * 68 + p0];
        float2 v0 = make_float2(d[nt][0] + Dh * x0.x, d[nt][1] + Dh * x0.y);
        float2 v1 = make_float2(d[nt][2] + Dh * x1.x, d[nt][3] + Dh * x1.y);
        *(float2*)&yo[(size_t)t0 * DINNER + p0] = v0;
        *(float2*)&yo[(size_t)t1 * DINNER + p0] = v1;
    }
}

// ---------------- 5) gate + RMSNorm (writes bf16 hi/lo planes) --------------
__global__ void __launch_bounds__(256) gate_rms_kernel(const float* __restrict__ norm_w)
{
    __shared__ float sh[8];
    int row = blockIdx.x, tid = threadIdx.x;
    const float4* y4 = (const float4*)(g_y  + (size_t)row * DINNER);
    const float4* z4 = (const float4*)(g_zx + (size_t)row * DINPROJ);
    float4 a0 = y4[tid], a1 = y4[tid + 256];
    float4 z0 = z4[tid], z1 = z4[tid + 256];
    float g[8];
    g[0] = a0.x * (z0.x / (1.f + expf(-z0.x)));
    g[1] = a0.y * (z0.y / (1.f + expf(-z0.y)));
    g[2] = a0.z * (z0.z / (1.f + expf(-z0.z)));
    g[3] = a0.w * (z0.w / (1.f + expf(-z0.w)));
    g[4] = a1.x * (z1.x / (1.f + expf(-z1.x)));
    g[5] = a1.y * (z1.y / (1.f + expf(-z1.y)));
    g[6] = a1.z * (z1.z / (1.f + expf(-z1.z)));
    g[7] = a1.w * (z1.w / (1.f + expf(-z1.w)));
    float ss = 0.f;
    #pragma unroll
    for (int j = 0; j < 8; j++) ss += g[j] * g[j];
    float tot = block_sum256(ss, sh);
    float inv = rsqrtf(tot * (1.f / DINNER) + 1e-5f);
    float4 w0 = ((const float4*)norm_w)[tid];
    float4 w1 = ((const float4*)norm_w)[tid + 256];
    float4 o0, o1;
    o0.x = g[0] * inv * w0.x; o0.y = g[1] * inv * w0.y;
    o0.z = g[2] * inv * w0.z; o0.w = g[3] * inv * w0.w;
    o1.x = g[4] * inv * w1.x; o1.y = g[5] * inv * w1.y;
    o1.z = g[6] * inv * w1.z; o1.w = g[7] * inv * w1.w;
    uint2 hi, lo;
    size_t idx = (size_t)row * DINNER + tid * 4;
    split4(o0, hi, lo);
    *(uint2*)(g_ynh + idx) = hi;
    *(uint2*)(g_ynl + idx) = lo;
    split4(o1, hi, lo);
    *(uint2*)(g_ynh + idx + 1024) = hi;
    *(uint2*)(g_ynl + idx + 1024) = lo;
}

// ---------------- launcher -------------------------------------------------
extern "C" void kernel_launch(void* const* d_in, const int* in_sizes, int n_in,
                              void* d_out, int out_size)
{
    const float* x       = (const float*)d_in[0];
    const float* ln_w    = (const float*)d_in[1];
    const float* ln_b    = (const float*)d_in[2];
    const float* W_in    = (const float*)d_in[3];
    const float* conv_w  = (const float*)d_in[4];
    const float* conv_b  = (const float*)d_in[5];
    const float* dt_bias = (const float*)d_in[6];
    const float* A_log   = (const float*)d_in[7];
    const float* Dp      = (const float*)d_in[8];
    const float* norm_w  = (const float*)d_in[9];
    const float* W_out   = (const float*)d_in[10];
    float* out = (float*)d_out;

    cudaFuncSetAttribute(gemm_tc<DINPROJ, DMODEL, false>,
                         cudaFuncAttributeMaxDynamicSharedMemorySize, SMEM_DYN);
    cudaFuncSetAttribute(gemm_tc<DMODEL, DINNER, true>,
                         cudaFuncAttributeMaxDynamicSharedMemorySize, SMEM_DYN);
    cudaFuncSetAttribute(s1_kernel,
                         cudaFuncAttributeMaxDynamicSharedMemorySize, S1_SMEMB);
    cudaFuncSetAttribute(s2_kernel,
                         cudaFuncAttributeMaxDynamicSharedMemorySize, S2N_B);

    uint16_t *wih, *wil, *woh, *wol;
    cudaGetSymbolAddress((void**)&wih, g_wih);
    cudaGetSymbolAddress((void**)&wil, g_wil);
    cudaGetSymbolAddress((void**)&woh, g_woh);
    cudaGetSymbolAddress((void**)&wol, g_wol);

    wsplit_kernel<<<(DINPROJ * DMODEL / 4 + 255) / 256, 256>>>(W_in, wih, wil,
                                                               DINPROJ * DMODEL / 4); // 1
    ln_kernel<<<BL, 256>>>(x, ln_w, ln_b);                          // 2

    gemm_tc<DINPROJ, DMODEL, false>                                 // 3
        <<<dim3((DINPROJ + 127) / 128, BL / 128), 256, SMEM_DYN>>>(nullptr, nullptr);

    conv_dt_kernel<<<dim3(9, BL), 256>>>(conv_w, conv_b, dt_bias);  // 4 <- ncu window

    wsplit_kernel<<<(DMODEL * DINNER / 4 + 255) / 256, 256>>>(W_out, woh, wol,
                                                              DMODEL * DINNER / 4);   // 5

    bcsplit_kernel<<<BATCH * NCHUNK, 256>>>();                      // 6

    s1_kernel<<<BATCH * NHEADS * 2, 256, S1_SMEMB>>>(A_log);        // 7

    s2_kernel<<<BATCH * NHEADS * NCHUNK, 256, S2N_B>>>(A_log, Dp);  // 8

    gate_rms_kernel<<<BL, 256>>>(norm_w);                           // 9

    gemm_tc<DMODEL, DINNER, true>                                   // 10
        <<<dim3(DMODEL / 128, BL / 128), 256, SMEM_DYN>>>(x, out);
}

// round 15
// speedup vs baseline: 1.0688x; 1.0465x over previous
#include <cuda_runtime.h>
#include <cstdint>
#include <math.h>

#define BATCH   2
#define SEQLEN  4096
#define DMODEL  1024
#define DINNER  2048
#define NHEADS  32
#define HEADDIM 64
#define DSTATE  64
#define CONVDIM 2176            // DINNER + 2*DSTATE
#define DINPROJ 4256            // 2*DINNER + 2*DSTATE + NHEADS
#define BL      8192            // BATCH*SEQLEN
#define CHUNK   64
#define NCHUNK  (SEQLEN / CHUNK)   // 64

// ---------------- scratch (static device globals: no allocations) ----------
__device__ float    g_zx  [(size_t)BL * DINPROJ];
__device__ float    g_xbca[(size_t)BL * CONVDIM];
__device__ float    g_dt  [(size_t)BL * NHEADS];
__device__ float    g_y   [(size_t)BL * DINNER];
// pre-split bf16 hi/lo operand planes
__device__ uint16_t g_uh  [(size_t)BL * DMODEL];
__device__ uint16_t g_ul  [(size_t)BL * DMODEL];
__device__ uint16_t g_ynh [(size_t)BL * DINNER];
__device__ uint16_t g_ynl [(size_t)BL * DINNER];
__device__ uint16_t g_wih [(size_t)DINPROJ * DMODEL];
__device__ uint16_t g_wil [(size_t)DINPROJ * DMODEL];
__device__ uint16_t g_woh [(size_t)DMODEL * DINNER];
__device__ uint16_t g_wol [(size_t)DMODEL * DINNER];
// scan pre-split planes
__device__ uint16_t g_bcsh[(size_t)BL * 128];                       // [t][B64|C64] hi
__device__ uint16_t g_bcsl[(size_t)BL * 128];
__device__ uint16_t g_bth [(size_t)BATCH * NCHUNK * 64 * 64];       // B^T [bc][n][t] hi
__device__ uint16_t g_btl [(size_t)BATCH * NCHUNK * 64 * 64];
__device__ uint16_t g_hch [(size_t)BATCH * NHEADS * NCHUNK * 4096]; // carry [p][n] hi
__device__ uint16_t g_hcl [(size_t)BATCH * NHEADS * NCHUNK * 4096];

// ---------------- helpers ---------------------------------------------------
__device__ __forceinline__ uint32_t smem_u32(const void* p) {
    uint32_t a;
    asm("{ .reg .u64 t; cvta.to.shared.u64 t, %1; cvt.u32.u64 %0, t; }"
        : "=r"(a) : "l"(p));
    return a;
}
// pack two f32 -> bf16x2 (first arg in LOW half)
__device__ __forceinline__ uint32_t packbf(float lo, float hi) {
    uint32_t r;
    asm("cvt.rn.bf16x2.f32 %0, %1, %2;" : "=r"(r) : "f"(hi), "f"(lo));
    return r;
}
// split float4 -> hi uint2 / lo uint2 (bf16x2 pairs)
__device__ __forceinline__ void split4(float4 v, uint2& hi, uint2& lo) {
    uint32_t h01 = packbf(v.x, v.y);
    uint32_t h23 = packbf(v.z, v.w);
    float rx = v.x - __uint_as_float(h01 << 16);
    float ry = v.y - __uint_as_float(h01 & 0xffff0000u);
    float rz = v.z - __uint_as_float(h23 << 16);
    float rw = v.w - __uint_as_float(h23 & 0xffff0000u);
    hi = make_uint2(h01, h23);
    lo = make_uint2(packbf(rx, ry), packbf(rz, rw));
}
__device__ __forceinline__ void split2(float a, float b, uint32_t& hi, uint32_t& lo) {
    hi = packbf(a, b);
    float ra = a - __uint_as_float(hi << 16);
    float rb = b - __uint_as_float(hi & 0xffff0000u);
    lo = packbf(ra, rb);
}

#define MMA_BF16(d, a, b0, b1) \
    asm volatile("mma.sync.aligned.m16n8k16.row.col.f32.bf16.bf16.f32 " \
        "{%0,%1,%2,%3}, {%4,%5,%6,%7}, {%8,%9}, {%0,%1,%2,%3};" \
        : "+f"((d)[0]), "+f"((d)[1]), "+f"((d)[2]), "+f"((d)[3]) \
        : "r"((a)[0]), "r"((a)[1]), "r"((a)[2]), "r"((a)[3]), \
          "r"(b0), "r"(b1))

#define LDSM_X4(r, addr) \
    asm volatile("ldmatrix.sync.aligned.m8n8.x4.shared.b16 {%0,%1,%2,%3}, [%4];" \
        : "=r"((r)[0]), "=r"((r)[1]), "=r"((r)[2]), "=r"((r)[3]) : "r"(addr))

#define CP_ASYNC16(dst, src) \
    asm volatile("cp.async.ca.shared.global [%0], [%1], 16;" \
        :: "r"(dst), "l"(src) : "memory")
#define CP_ASYNC16_P(dst, src, nbytes) \
    asm volatile("cp.async.ca.shared.global [%0], [%1], 16, %2;" \
        :: "r"(dst), "l"(src), "r"(nbytes) : "memory")
#define CP_ASYNC4(dst, src) \
    asm volatile("cp.async.ca.shared.global [%0], [%1], 4;" \
        :: "r"(dst), "l"(src) : "memory")
#define CP_COMMIT() asm volatile("cp.async.commit_group;" ::: "memory")
#define CP_WAIT0()  asm volatile("cp.async.wait_group 0;" ::: "memory")
#define CP_WAIT1()  asm volatile("cp.async.wait_group 1;" ::: "memory")

// -------- weight split kernel: fp32 -> bf16 hi/lo ---------------------------
__global__ void __launch_bounds__(256) wsplit_kernel(const float* __restrict__ src,
                                                     uint16_t* __restrict__ dh,
                                                     uint16_t* __restrict__ dl,
                                                     int n4)
{
    int i = blockIdx.x * 256 + threadIdx.x;
    if (i < n4) {
        float4 v = ((const float4*)src)[i];
        uint2 hi, lo;
        split4(v, hi, lo);
        ((uint2*)dh)[i] = hi;
        ((uint2*)dl)[i] = lo;
    }
}

// =============== bf16x3 emulated-fp32 NT GEMM (cp.async + LDSM) ============
#define KT        32
#define RSU       20                       // row stride (uint32 pairs, 80 B)
#define PL_AHI    0
#define PL_ALO    2560
#define PL_BHI    5120
#define PL_BLO    7680
#define STAGE_U   10240                    // uint32 per stage
#define SMEM_DYN  (2 * STAGE_U * 4)        // 81920 bytes

template<int N, int K, bool SECOND>
__global__ void __launch_bounds__(256, 2) gemm_tc(const float* __restrict__ resid,
                                                  float* __restrict__ outp)
{
    extern __shared__ uint32_t smu[];
    const uint16_t* __restrict__ Ah = SECOND ? g_ynh : g_uh;
    const uint16_t* __restrict__ Al = SECOND ? g_ynl : g_ul;
    const uint16_t* __restrict__ Wh = SECOND ? g_woh : g_wih;
    const uint16_t* __restrict__ Wl = SECOND ? g_wol : g_wil;
    float* __restrict__ Cptr        = SECOND ? outp : g_zx;

    int tid = threadIdx.x;
    int wid = tid >> 5, lane = tid & 31;
    int bm = blockIdx.y, bn = blockIdx.x;

    uint32_t sb = smem_u32(smu);

    int rA = tid >> 2, cA = (tid & 3) * 16;       // row 0..63, byte chunk
    const int NKT = K / KT;
    auto issue = [&](int kt) {
        if (kt < NKT) {
            uint32_t dst = sb + (uint32_t)(kt & 1) * (STAGE_U * 4);
            #pragma unroll
            for (int i = 0; i < 2; i++) {
                int row = rA + i * 64;
                uint32_t so = (uint32_t)(row * (RSU * 4)) + cA;
                size_t ao = (size_t)(bm * 128 + row) * K + kt * KT + (cA >> 1);
                CP_ASYNC16(dst + PL_AHI * 4 + so, Ah + ao);
                CP_ASYNC16(dst + PL_ALO * 4 + so, Al + ao);
                int nrow = bn * 128 + row;
                int nb = (nrow < N) ? 16 : 0;
                size_t bo = (size_t)nrow * K + kt * KT + (cA >> 1);
                CP_ASYNC16_P(dst + PL_BHI * 4 + so, Wh + bo, nb);
                CP_ASYNC16_P(dst + PL_BLO * 4 + so, Wl + bo, nb);
            }
        }
        CP_COMMIT();
    };

    int wm = wid >> 1, wn = wid & 1;
    int g = lane >> 2, t4 = lane & 3;

    uint32_t aoff = (uint32_t)(((wm * 32 + (lane & 15)) * RSU + 4 * (lane >> 4)) * 4);
    uint32_t boff = (uint32_t)(((wn * 64 + 8 * (lane >> 4) + (lane & 7)) * RSU
                                + 4 * ((lane >> 3) & 1)) * 4);

    float d[2][8][4];
    #pragma unroll
    for (int mt = 0; mt < 2; mt++)
        #pragma unroll
        for (int nt = 0; nt < 8; nt++)
            #pragma unroll
            for (int j = 0; j < 4; j++) d[mt][nt][j] = 0.f;

    issue(0);

    #pragma unroll 1
    for (int kt = 0; kt < NKT; ++kt) {
        issue(kt + 1);
        if (kt + 1 < NKT) CP_WAIT1(); else CP_WAIT0();
        __syncthreads();

        uint32_t base = sb + (uint32_t)(kt & 1) * (STAGE_U * 4);
        #pragma unroll
        for (int ks = 0; ks < 2; ks++) {
            uint32_t kby = (uint32_t)(ks * 8 * 4);
            uint32_t ah[2][4], al[2][4];
            #pragma unroll
            for (int mt = 0; mt < 2; mt++) {
                uint32_t aa = base + aoff + (uint32_t)(mt * 16 * RSU * 4) + kby;
                LDSM_X4(ah[mt], aa + PL_AHI * 4);
                LDSM_X4(al[mt], aa + PL_ALO * 4);
            }
            #pragma unroll
            for (int ntp = 0; ntp < 4; ntp++) {
                uint32_t ba = base + boff + (uint32_t)(ntp * 16 * RSU * 4) + kby;
                uint32_t bh[4], bl[4];
                LDSM_X4(bh, ba + PL_BHI * 4);
                LDSM_X4(bl, ba + PL_BLO * 4);
                #pragma unroll
                for (int mt = 0; mt < 2; mt++) {
                    MMA_BF16(d[mt][2*ntp],   ah[mt], bh[0], bh[1]);
                    MMA_BF16(d[mt][2*ntp],   ah[mt], bl[0], bl[1]);
                    MMA_BF16(d[mt][2*ntp],   al[mt], bh[0], bh[1]);
                    MMA_BF16(d[mt][2*ntp+1], ah[mt], bh[2], bh[3]);
                    MMA_BF16(d[mt][2*ntp+1], ah[mt], bl[2], bl[3]);
                    MMA_BF16(d[mt][2*ntp+1], al[mt], bh[2], bh[3]);
                }
            }
        }
        __syncthreads();
    }

    #pragma unroll
    for (int mt = 0; mt < 2; mt++) {
        int row = bm * 128 + wm * 32 + mt * 16 + g;
        #pragma unroll
        for (int nt = 0; nt < 8; nt++) {
            int col = bn * 128 + wn * 64 + nt * 8 + t4 * 2;
            if (col < N) {
                size_t i0 = (size_t)row * N + col;
                size_t i1 = (size_t)(row + 8) * N + col;
                float2 v0 = make_float2(d[mt][nt][0], d[mt][nt][1]);
                float2 v1 = make_float2(d[mt][nt][2], d[mt][nt][3]);
                if (SECOND) {
                    float2 r0v = *(const float2*)(resid + i0);
                    float2 r1v = *(const float2*)(resid + i1);
                    v0.x += r0v.x; v0.y += r0v.y;
                    v1.x += r1v.x; v1.y += r1v.y;
                }
                *(float2*)(Cptr + i0) = v0;
                *(float2*)(Cptr + i1) = v1;
            }
        }
    }
}

// ---------------- block reduction helper -----------------------------------
__device__ __forceinline__ float block_sum256(float v, float* sh) {
    #pragma unroll
    for (int o = 16; o; o >>= 1) v += __shfl_xor_sync(0xffffffffu, v, o);
    int lane = threadIdx.x & 31, wid = threadIdx.x >> 5;
    __syncthreads();
    if (lane == 0) sh[wid] = v;
    __syncthreads();
    float tt = 0.f;
    #pragma unroll
    for (int j = 0; j < 8; j++) tt += sh[j];
    return tt;
}

// ---------------- 1) LayerNorm (writes bf16 hi/lo planes) -------------------
__global__ void __launch_bounds__(256) ln_kernel(const float* __restrict__ x,
                                                 const float* __restrict__ w,
                                                 const float* __restrict__ bparm)
{
    __shared__ float sh[8];
    int row = blockIdx.x, tid = threadIdx.x;
    const float4* xr = (const float4*)(x + (size_t)row * DMODEL);
    float4 v = xr[tid];
    float s  = v.x + v.y + v.z + v.w;
    float mu = block_sum256(s, sh) * (1.f / DMODEL);
    float d0 = v.x - mu, d1 = v.y - mu, d2 = v.z - mu, d3 = v.w - mu;
    float vs = d0*d0 + d1*d1 + d2*d2 + d3*d3;
    float var = block_sum256(vs, sh) * (1.f / DMODEL);
    float inv = rsqrtf(var + 1e-5f);
    float4 wv = ((const float4*)w)[tid];
    float4 bv = ((const float4*)bparm)[tid];
    float4 o;
    o.x = d0 * inv * wv.x + bv.x;
    o.y = d1 * inv * wv.y + bv.y;
    o.z = d2 * inv * wv.z + bv.z;
    o.w = d3 * inv * wv.w + bv.w;
    uint2 hi, lo;
    split4(o, hi, lo);
    size_t idx = (size_t)row * DMODEL + tid * 4;
    *(uint2*)(g_uh + idx) = hi;
    *(uint2*)(g_ul + idx) = lo;
}

// ---------------- 3) rolling-window conv(4)+SiLU, fused softplus(dt) -------
// Thread owns one channel for 16 consecutive rows; 3-tap history in regs.
// Loads/output: 19/16 (vs 4). 16-row tiles never cross the batch boundary.
__global__ void __launch_bounds__(256) conv_dt_kernel(const float* __restrict__ conv_w,
                                                      const float* __restrict__ conv_b,
                                                      const float* __restrict__ dt_bias)
{
    int c  = blockIdx.x * 256 + threadIdx.x;
    int i0 = blockIdx.y * 16;                 // first global row of tile
    int b  = i0 >> 12;
    int l0 = i0 & 4095;
    if (c < CONVDIM) {
        float w0 = conv_w[c*4+0], w1 = conv_w[c*4+1];
        float w2 = conv_w[c*4+2], w3 = conv_w[c*4+3];
        float bias = conv_b[c];
        const float* col = g_zx + ((size_t)b << 12) * DINPROJ + DINNER + c;
        float xm3 = (l0 >= 3) ? col[(size_t)(l0-3) * DINPROJ] : 0.f;
        float xm2 = (l0 >= 2) ? col[(size_t)(l0-2) * DINPROJ] : 0.f;
        float xm1 = (l0 >= 1) ? col[(size_t)(l0-1) * DINPROJ] : 0.f;
        #pragma unroll
        for (int j = 0; j < 16; j++) {
            float x0 = col[(size_t)(l0 + j) * DINPROJ];
            float s = bias + xm3 * w0 + xm2 * w1 + xm1 * w2 + x0 * w3;
            s = s / (1.f + expf(-s));
            g_xbca[(size_t)(i0 + j) * CONVDIM + c] = s;
            xm3 = xm2; xm2 = xm1; xm1 = x0;
        }
    } else if (c < CONVDIM + NHEADS) {
        int hh = c - CONVDIM;
        float bias = dt_bias[hh];
        const float* src = g_zx + (size_t)i0 * DINPROJ + (DINNER + CONVDIM) + hh;
        #pragma unroll
        for (int j = 0; j < 16; j++) {
            float v = src[(size_t)j * DINPROJ] + bias;
            g_dt[(size_t)(i0 + j) * NHEADS + hh] = (v > 20.f) ? v : log1pf(expf(v));
        }
    }
}

// ---------------- 3b) BC split: straight [t][128] + transposed B [n][t] -----
__global__ void __launch_bounds__(256) bcsplit_kernel()
{
    __shared__ float sb[64][132];
    int bc = blockIdx.x;                  // b*NCHUNK + chunk (rows bc*64..+63)
    int tid = threadIdx.x;
    const float* src = g_xbca + (size_t)bc * 64 * CONVDIM + 2048;
    #pragma unroll
    for (int i = 0; i < 8; i++) {
        int idx = tid + i * 256;          // 2048 float4
        int t = idx >> 5, c4 = (idx & 31) * 4;
        float4 v = *(const float4*)(src + (size_t)t * CONVDIM + c4);
        uint2 hi, lo;
        split4(v, hi, lo);
        size_t o = ((size_t)(bc * 64 + t)) * 128 + c4;
        *(uint2*)(g_bcsh + o) = hi;
        *(uint2*)(g_bcsl + o) = lo;
        *(float4*)&sb[t][c4] = v;
    }
    __syncthreads();
    // transposed B (cols 0..63 of BC region): output row n, 64 t values
    int n = tid >> 2, tg = (tid & 3) * 16;
    uint32_t hi[8], lo[8];
    #pragma unroll
    for (int j = 0; j < 8; j++)
        split2(sb[tg + 2*j][n], sb[tg + 2*j + 1][n], hi[j], lo[j]);
    size_t o = ((size_t)bc * 64 + n) * 64 + tg;
    *(uint4*)(g_bth + o)     = make_uint4(hi[0], hi[1], hi[2], hi[3]);
    *(uint4*)(g_bth + o + 8) = make_uint4(hi[4], hi[5], hi[6], hi[7]);
    *(uint4*)(g_btl + o)     = make_uint4(lo[0], lo[1], lo[2], lo[3]);
    *(uint4*)(g_btl + o + 8) = make_uint4(lo[4], lo[5], lo[6], lo[7]);
}

// -------- warp-0 inclusive scan of 64 s-values (dt*Ah) -> cum[64] ----------
__device__ __forceinline__ void scan64(const float* dtv, float Ah, float* cum, int tid) {
    if (tid < 32) {
        float a = dtv[tid] * Ah;
        float b = dtv[32 + tid] * Ah;
        #pragma unroll
        for (int o = 1; o < 32; o <<= 1) {
            float ta = __shfl_up_sync(0xffffffffu, a, o);
            float tb = __shfl_up_sync(0xffffffffu, b, o);
            if (tid >= o) { a += ta; b += tb; }
        }
        float totA = __shfl_sync(0xffffffffu, a, 31);
        cum[tid]      = a;
        cum[32 + tid] = totA + b;
    }
}

// ---------------- 4a) S1: chunk-state pass (bf16x3 MMA, pre-split B^T) -----
#define S1_XF    0                          // fp32 X [64][68]
#define S1_BT    4352                       // B^T hi [32 n][36] u32
#define S1_BTLO  5504
#define S1_DT    6656
#define S1_BUF   6720                       // ring buffer (x2)
#define S1_XWT   13440                      // XWT hi [64 p][36] u32
#define S1_XWTLO 15744
#define S1_W     18048
#define S1_CUM   18112
#define S1_SMEMF 18176
#define S1_SMEMB (S1_SMEMF * 4)             // 72704 bytes

__global__ void __launch_bounds__(256) s1_kernel(const float* __restrict__ A_log)
{
    extern __shared__ float sm[];
    uint32_t* su = (uint32_t*)sm;
    int bx = blockIdx.x;
    int b = bx >> 6, h = (bx >> 1) & 31, nh = bx & 1;
    int tid = threadIdx.x;
    int wid = tid >> 5, lane = tid & 31;
    int wm = wid & 1, wn = wid >> 1;        // n-tile (16), p-quarter (16)
    int g = lane >> 2, t4 = lane & 3;
    float Ah = -expf(A_log[h]);

    float* w   = sm + S1_W;
    float* cum = sm + S1_CUM;
    uint32_t sbase = smem_u32(sm);

    const float* base = g_xbca + (size_t)b * SEQLEN * CONVDIM;
    const float* dtb  = g_dt   + (size_t)b * SEQLEN * NHEADS + h;

    auto issue = [&](int c) {
        if (c < NCHUNK) {
            uint32_t dst = sbase + (uint32_t)(c & 1) * (S1_BUF * 4);
            const float* rowb = base + (size_t)c * CHUNK * CONVDIM;
            #pragma unroll
            for (int i = 0; i < 4; i++) {              // X fp32: 1024 f4
                int f4 = tid + i * 256;
                int t = f4 >> 4, j = (f4 & 15) * 4;
                CP_ASYNC16(dst + (uint32_t)(t * 68 + j) * 4,
                           rowb + (size_t)t * CONVDIM + h * 64 + j);
            }
            {                                          // B^T planes
                int n = tid >> 3, ch = tid & 7;
                size_t src = ((size_t)(b * NCHUNK + c) * 64 + nh * 32 + n) * 64 + ch * 8;
                uint32_t so = (uint32_t)(n * 36 + ch * 4) * 4;
                CP_ASYNC16(dst + S1_BT * 4 + so, g_bth + src);
                CP_ASYNC16(dst + S1_BTLO * 4 + so, g_btl + src);
            }
            if (tid < 64)
                CP_ASYNC4(dst + S1_DT * 4 + tid * 4,
                          dtb + (size_t)(c * CHUNK + tid) * NHEADS);
        }
        CP_COMMIT();
    };

    float d0[4] = {0.f, 0.f, 0.f, 0.f};
    float d1[4] = {0.f, 0.f, 0.f, 0.f};

    issue(0); issue(1);

    for (int c = 0; c < NCHUNK; c++) {
        CP_WAIT1();
        __syncthreads();
        float* S = sm + (c & 1) * S1_BUF;
        uint32_t* SU = su + (c & 1) * S1_BUF;

        scan64(S + S1_DT, Ah, cum, tid);
        __syncthreads();

        float cl = cum[63];
        float E  = expf(cl);
        if (tid < 64) w[tid] = expf(cl - cum[tid]) * S[S1_DT + tid];

        // carry store (state at chunk start) as bf16 hi/lo planes [p][n]
        {
            size_t hcb = (((size_t)(b * 32 + h)) * NCHUNK + c) * 4096;
            int n0 = nh * 32 + wm * 16 + g;
            int p0 = wn * 16 + 2 * t4;
            auto stbf = [&](int p, int n, float v) {
                uint32_t hb = packbf(v, v);
                float l = v - __uint_as_float(hb << 16);
                uint32_t lb = packbf(l, l);
                size_t a = hcb + (size_t)p * 64 + n;
                g_hch[a] = (uint16_t)hb;
                g_hcl[a] = (uint16_t)lb;
            };
            stbf(p0,     n0,     d0[0]); stbf(p0 + 1, n0,     d0[1]);
            stbf(p0,     n0 + 8, d0[2]); stbf(p0 + 1, n0 + 8, d0[3]);
            stbf(p0 + 8, n0,     d1[0]); stbf(p0 + 9, n0,     d1[1]);
            stbf(p0 + 8, n0 + 8, d1[2]); stbf(p0 + 9, n0 + 8, d1[3]);
        }
        #pragma unroll
        for (int j = 0; j < 4; j++) { d0[j] *= E; d1[j] *= E; }
        __syncthreads();                      // w ready; prev XWT reads done

        // build XWT planes: [p][t-pairs], value = w_t * X[t][p]
        {
            int p = tid & 63, tq = tid >> 6;
            uint32_t hi[8], lo[8];
            #pragma unroll
            for (int q = 0; q < 8; q++) {
                int t0 = tq * 16 + 2 * q;
                float a = S[t0 * 68 + p] * w[t0];
                float bb = S[(t0 + 1) * 68 + p] * w[t0 + 1];
                split2(a, bb, hi[q], lo[q]);
            }
            int o = S1_XWT + p * 36 + tq * 8;
            *(uint4*)&su[o]            = make_uint4(hi[0], hi[1], hi[2], hi[3]);
            *(uint4*)&su[o + 4]        = make_uint4(hi[4], hi[5], hi[6], hi[7]);
            *(uint4*)&su[o + 2304]     = make_uint4(lo[0], lo[1], lo[2], lo[3]);
            *(uint4*)&su[o + 2304 + 4] = make_uint4(lo[4], lo[5], lo[6], lo[7]);
        }
        __syncthreads();                      // XWT ready

        // MMA: dd[pb] += B^T(n,t) x XWT(p,t)^T
        const uint32_t* BT = SU + S1_BT;
        #pragma unroll
        for (int kc = 0; kc < 4; kc++) {
            int o0 = (wm * 16 + g) * 36 + kc * 8 + t4;
            int o1 = o0 + 8 * 36;
            uint32_t ah[4], al[4];
            ah[0] = BT[o0];     ah[1] = BT[o1];
            ah[2] = BT[o0 + 4]; ah[3] = BT[o1 + 4];
            al[0] = BT[1152 + o0];     al[1] = BT[1152 + o1];
            al[2] = BT[1152 + o0 + 4]; al[3] = BT[1152 + o1 + 4];
            #pragma unroll
            for (int pb = 0; pb < 2; pb++) {
                int pr = S1_XWT + (wn * 16 + pb * 8 + g) * 36 + kc * 8 + t4;
                uint32_t bh0 = su[pr], bh1 = su[pr + 4];
                uint32_t bl0 = su[pr + 2304], bl1 = su[pr + 2304 + 4];
                float* dd = pb ? d1 : d0;
                MMA_BF16(dd, ah, bh0, bh1);
                MMA_BF16(dd, ah, bl0, bl1);
                MMA_BF16(dd, al, bh0, bh1);
            }
        }
        __syncthreads();                      // reads done before restage
        issue(c + 2);
    }
}

// ---------------- 4b) S2: per-chunk parallel y (bf16x3 MMA, pre-split) ------
#define P_A     0          // C hi (later G hi)
#define P_ALO   2304
#define P_B     4608
#define P_BLO   6912
#define P_C2    9216
#define P_C2LO  11520
#define P_XT    13824
#define P_XTLO  16128
#define P_HT    18432
#define P_HTLO  20736
#define P_XF    23040      // fp32 X tile [64][68]
#define P_DT2   27392
#define P_CUM2  27456
#define S2N_U   27520
#define S2N_B   (S2N_U * 4)   // 110080 bytes

__global__ void __launch_bounds__(256) s2_kernel(const float* __restrict__ A_log,
                                                 const float* __restrict__ Dp)
{
    extern __shared__ uint32_t su[];
    float* sf = (float*)su;
    int bx = blockIdx.x;
    int c = bx & 63, h = (bx >> 6) & 31, b = bx >> 11;
    int tid = threadIdx.x;
    int wid = tid >> 5, lane = tid & 31;
    int wm = wid >> 1, wn = wid & 1;        // 4x2 warp grid, warp tile 16x32
    int g = lane >> 2, t4 = lane & 3;
    float Ah = -expf(A_log[h]);
    float Dh = Dp[h];

    uint32_t sb = smem_u32(su);
    const float* rowb = g_xbca + ((size_t)b * SEQLEN + c * 64) * CONVDIM;

    // ---- async loads: C/B planes, HT planes, X fp32, dt --------------------
    {
        int r = tid >> 2, q = tid & 3;
        size_t ib = ((size_t)(b * SEQLEN + c * 64 + r)) * 128;
        size_t hb = (((size_t)(b * 32 + h)) * NCHUNK + c) * 4096 + (size_t)r * 64;
        #pragma unroll
        for (int k = 0; k < 2; k++) {
            int ch = q * 2 + k;
            uint32_t so = (uint32_t)(r * 36 + ch * 4) * 4;
            CP_ASYNC16(sb + P_A * 4 + so,    g_bcsh + ib + 64 + ch * 8);
            CP_ASYNC16(sb + P_ALO * 4 + so,  g_bcsl + ib + 64 + ch * 8);
            CP_ASYNC16(sb + P_B * 4 + so,    g_bcsh + ib + ch * 8);
            CP_ASYNC16(sb + P_BLO * 4 + so,  g_bcsl + ib + ch * 8);
            CP_ASYNC16(sb + P_HT * 4 + so,   g_hch + hb + ch * 8);
            CP_ASYNC16(sb + P_HTLO * 4 + so, g_hcl + hb + ch * 8);
        }
        #pragma unroll
        for (int i = 0; i < 4; i++) {
            int f4 = tid + i * 256;
            int t = f4 >> 4, j = (f4 & 15) * 4;
            CP_ASYNC16(sb + (uint32_t)(P_XF + t * 68 + j) * 4,
                       rowb + (size_t)t * CONVDIM + h * 64 + j);
        }
        if (tid < 64)
            CP_ASYNC4(sb + (uint32_t)(P_DT2 + tid) * 4,
                      g_dt + ((size_t)b * SEQLEN + c * 64 + tid) * NHEADS + h);
        CP_COMMIT();
    }

    // fp32 C rows for C2 (independent regular loads)
    int r = tid >> 2;
    int cg = (tid & 3) * 16;
    float4 cre[4];
    #pragma unroll
    for (int i = 0; i < 4; i++)
        cre[i] = *(const float4*)(rowb + (size_t)r * CONVDIM + 2112 + cg + 4 * i);

    CP_WAIT0();
    __syncthreads();

    scan64(sf + P_DT2, Ah, sf + P_CUM2, tid);
    __syncthreads();

    // ---- C2 = Et*C planes, XT planes ---------------------------------------
    {
        float Et = expf(sf[P_CUM2 + r]);
        #pragma unroll
        for (int i = 0; i < 4; i++) {
            float4 v = cre[i];
            v.x *= Et; v.y *= Et; v.z *= Et; v.w *= Et;
            uint2 hi, lo;
            split4(v, hi, lo);
            int col = cg + 4 * i;
            *(uint2*)&su[P_C2 + r * 36 + col / 2]          = hi;
            *(uint2*)&su[P_C2 + 2304 + r * 36 + col / 2]   = lo;
        }
    }
    {
        int p = tid & 63, tq = tid >> 6;
        uint32_t hi[8], lo[8];
        #pragma unroll
        for (int q = 0; q < 8; q++) {
            int t0 = tq * 16 + 2 * q;
            split2(sf[P_XF + t0 * 68 + p], sf[P_XF + (t0 + 1) * 68 + p], hi[q], lo[q]);
        }
        int o = P_XT + p * 36 + tq * 8;
        *(uint4*)&su[o]            = make_uint4(hi[0], hi[1], hi[2], hi[3]);
        *(uint4*)&su[o + 4]        = make_uint4(hi[4], hi[5], hi[6], hi[7]);
        *(uint4*)&su[o + 2304]     = make_uint4(lo[0], lo[1], lo[2], lo[3]);
        *(uint4*)&su[o + 2304 + 4] = make_uint4(lo[4], lo[5], lo[6], lo[7]);
    }
    __syncthreads();

    auto mm = [&](uint32_t offA, uint32_t offB, float (*dd)[4]) {
        #pragma unroll
        for (int ks = 0; ks < 4; ks++) {
            int kb = ks * 8;
            uint32_t ah[4], al[4];
            int o0 = (wm * 16 + g) * 36 + kb + t4;
            int o1 = o0 + 8 * 36;
            ah[0] = su[offA + o0];     ah[1] = su[offA + o1];
            ah[2] = su[offA + o0 + 4]; ah[3] = su[offA + o1 + 4];
            al[0] = su[offA + 2304 + o0];     al[1] = su[offA + 2304 + o1];
            al[2] = su[offA + 2304 + o0 + 4]; al[3] = su[offA + 2304 + o1 + 4];
            #pragma unroll
            for (int nt = 0; nt < 4; nt++) {
                int ob = (wn * 32 + nt * 8 + g) * 36 + kb + t4;
                uint32_t bh0 = su[offB + ob], bh1 = su[offB + ob + 4];
                uint32_t bl0 = su[offB + 2304 + ob], bl1 = su[offB + 2304 + ob + 4];
                MMA_BF16(dd[nt], ah, bh0, bh1);
                MMA_BF16(dd[nt], ah, bl0, bl1);
                MMA_BF16(dd[nt], al, bh0, bh1);
            }
        }
    };

    float d[4][4];
    #pragma unroll
    for (int nt = 0; nt < 4; nt++)
        #pragma unroll
        for (int j = 0; j < 4; j++) d[nt][j] = 0.f;
    mm(P_A, P_B, d);

    int t0 = wm * 16 + g, t1 = t0 + 8;
    float ct0 = sf[P_CUM2 + t0], ct1 = sf[P_CUM2 + t1];
    float gv[4][4];
    #pragma unroll
    for (int nt = 0; nt < 4; nt++) {
        int s0 = wn * 32 + nt * 8 + 2 * t4, s1 = s0 + 1;
        float cs0 = sf[P_CUM2 + s0], cs1 = sf[P_CUM2 + s1];
        float w0 = sf[P_DT2 + s0],  w1 = sf[P_DT2 + s1];
        gv[nt][0] = (s0 <= t0) ? d[nt][0] * expf(ct0 - cs0) * w0 : 0.f;
        gv[nt][1] = (s1 <= t0) ? d[nt][1] * expf(ct0 - cs1) * w1 : 0.f;
        gv[nt][2] = (s0 <= t1) ? d[nt][2] * expf(ct1 - cs0) * w0 : 0.f;
        gv[nt][3] = (s1 <= t1) ? d[nt][3] * expf(ct1 - cs1) * w1 : 0.f;
    }
    __syncthreads();

    #pragma unroll
    for (int nt = 0; nt < 4; nt++) {
        int pi = wn * 16 + nt * 4 + t4;
        uint32_t h01, l01, h23, l23;
        split2(gv[nt][0], gv[nt][1], h01, l01);
        split2(gv[nt][2], gv[nt][3], h23, l23);
        su[P_A   + t0 * 36 + pi] = h01;
        su[P_ALO + t0 * 36 + pi] = l01;
        su[P_A   + t1 * 36 + pi] = h23;
        su[P_ALO + t1 * 36 + pi] = l23;
    }
    __syncthreads();

    #pragma unroll
    for (int nt = 0; nt < 4; nt++)
        #pragma unroll
        for (int j = 0; j < 4; j++) d[nt][j] = 0.f;
    mm(P_A, P_XT, d);
    mm(P_C2, P_HT, d);

    float* yo = g_y + ((size_t)b * SEQLEN + c * 64) * DINNER + h * 64;
    #pragma unroll
    for (int nt = 0; nt < 4; nt++) {
        int p0 = wn * 32 + nt * 8 + 2 * t4;
        float2 x0 = *(const float2*)&sf[P_XF + t0 * 68 + p0];
        float2 x1 = *(const float2*)&sf[P_XF + t1 * 68 + p0];
        float2 v0 = make_float2(d[nt][0] + Dh * x0.x, d[nt][1] + Dh * x0.y);
        float2 v1 = make_float2(d[nt][2] + Dh * x1.x, d[nt][3] + Dh * x1.y);
        *(float2*)&yo[(size_t)t0 * DINNER + p0] = v0;
        *(float2*)&yo[(size_t)t1 * DINNER + p0] = v1;
    }
}

// ---------------- 5) gate + RMSNorm (writes bf16 hi/lo planes) --------------
__global__ void __launch_bounds__(256) gate_rms_kernel(const float* __restrict__ norm_w)
{
    __shared__ float sh[8];
    int row = blockIdx.x, tid = threadIdx.x;
    const float4* y4 = (const float4*)(g_y  + (size_t)row * DINNER);
    const float4* z4 = (const float4*)(g_zx + (size_t)row * DINPROJ);
    float4 a0 = y4[tid], a1 = y4[tid + 256];
    float4 z0 = z4[tid], z1 = z4[tid + 256];
    float g[8];
    g[0] = a0.x * (z0.x / (1.f + expf(-z0.x)));
    g[1] = a0.y * (z0.y / (1.f + expf(-z0.y)));
    g[2] = a0.z * (z0.z / (1.f + expf(-z0.z)));
    g[3] = a0.w * (z0.w / (1.f + expf(-z0.w)));
    g[4] = a1.x * (z1.x / (1.f + expf(-z1.x)));
    g[5] = a1.y * (z1.y / (1.f + expf(-z1.y)));
    g[6] = a1.z * (z1.z / (1.f + expf(-z1.z)));
    g[7] = a1.w * (z1.w / (1.f + expf(-z1.w)));
    float ss = 0.f;
    #pragma unroll
    for (int j = 0; j < 8; j++) ss += g[j] * g[j];
    float tot = block_sum256(ss, sh);
    float inv = rsqrtf(tot * (1.f / DINNER) + 1e-5f);
    float4 w0 = ((const float4*)norm_w)[tid];
    float4 w1 = ((const float4*)norm_w)[tid + 256];
    float4 o0, o1;
    o0.x = g[0] * inv * w0.x; o0.y = g[1] * inv * w0.y;
    o0.z = g[2] * inv * w0.z; o0.w = g[3] * inv * w0.w;
    o1.x = g[4] * inv * w1.x; o1.y = g[5] * inv * w1.y;
    o1.z = g[6] * inv * w1.z; o1.w = g[7] * inv * w1.w;
    uint2 hi, lo;
    size_t idx = (size_t)row * DINNER + tid * 4;
    split4(o0, hi, lo);
    *(uint2*)(g_ynh + idx) = hi;
    *(uint2*)(g_ynl + idx) = lo;
    split4(o1, hi, lo);
    *(uint2*)(g_ynh + idx + 1024) = hi;
    *(uint2*)(g_ynl + idx + 1024) = lo;
}

// ---------------- launcher -------------------------------------------------
extern "C" void kernel_launch(void* const* d_in, const int* in_sizes, int n_in,
                              void* d_out, int out_size)
{
    const float* x       = (const float*)d_in[0];
    const float* ln_w    = (const float*)d_in[1];
    const float* ln_b    = (const float*)d_in[2];
    const float* W_in    = (const float*)d_in[3];
    const float* conv_w  = (const float*)d_in[4];
    const float* conv_b  = (const float*)d_in[5];
    const float* dt_bias = (const float*)d_in[6];
    const float* A_log   = (const float*)d_in[7];
    const float* Dp      = (const float*)d_in[8];
    const float* norm_w  = (const float*)d_in[9];
    const float* W_out   = (const float*)d_in[10];
    float* out = (float*)d_out;

    cudaFuncSetAttribute(gemm_tc<DINPROJ, DMODEL, false>,
                         cudaFuncAttributeMaxDynamicSharedMemorySize, SMEM_DYN);
    cudaFuncSetAttribute(gemm_tc<DMODEL, DINNER, true>,
                         cudaFuncAttributeMaxDynamicSharedMemorySize, SMEM_DYN);
    cudaFuncSetAttribute(s1_kernel,
                         cudaFuncAttributeMaxDynamicSharedMemorySize, S1_SMEMB);
    cudaFuncSetAttribute(s2_kernel,
                         cudaFuncAttributeMaxDynamicSharedMemorySize, S2N_B);

    uint16_t *wih, *wil, *woh, *wol;
    cudaGetSymbolAddress((void**)&wih, g_wih);
    cudaGetSymbolAddress((void**)&wil, g_wil);
    cudaGetSymbolAddress((void**)&woh, g_woh);
    cudaGetSymbolAddress((void**)&wol, g_wol);

    wsplit_kernel<<<(DINPROJ * DMODEL / 4 + 255) / 256, 256>>>(W_in, wih, wil,
                                                               DINPROJ * DMODEL / 4); // 1
    ln_kernel<<<BL, 256>>>(x, ln_w, ln_b);                          // 2

    gemm_tc<DINPROJ, DMODEL, false>                                 // 3
        <<<dim3((DINPROJ + 127) / 128, BL / 128), 256, SMEM_DYN>>>(nullptr, nullptr);

    conv_dt_kernel<<<dim3(9, BL / 16), 256>>>(conv_w, conv_b, dt_bias); // 4 <- ncu window

    wsplit_kernel<<<(DMODEL * DINNER / 4 + 255) / 256, 256>>>(W_out, woh, wol,
                                                              DMODEL * DINNER / 4);   // 5

    bcsplit_kernel<<<BATCH * NCHUNK, 256>>>();                      // 6

    s1_kernel<<<BATCH * NHEADS * 2, 256, S1_SMEMB>>>(A_log);        // 7

    s2_kernel<<<BATCH * NHEADS * NCHUNK, 256, S2N_B>>>(A_log, Dp);  // 8

    gate_rms_kernel<<<BL, 256>>>(norm_w);                           // 9

    gemm_tc<DMODEL, DINNER, true>                                   // 10
        <<<dim3(DMODEL / 128, BL / 128), 256, SMEM_DYN>>>(x, out);
}

// round 16
// speedup vs baseline: 1.0725x; 1.0035x over previous
#include <cuda_runtime.h>
#include <cstdint>
#include <math.h>

#define BATCH   2
#define SEQLEN  4096
#define DMODEL  1024
#define DINNER  2048
#define NHEADS  32
#define HEADDIM 64
#define DSTATE  64
#define CONVDIM 2176            // DINNER + 2*DSTATE
#define DINPROJ 4256            // 2*DINNER + 2*DSTATE + NHEADS
#define BL      8192            // BATCH*SEQLEN
#define CHUNK   64
#define NCHUNK  (SEQLEN / CHUNK)   // 64

// ---------------- scratch (static device globals: no allocations) ----------
__device__ float    g_zx  [(size_t)BL * DINPROJ];
__device__ float    g_xbca[(size_t)BL * CONVDIM];
__device__ float    g_dt  [(size_t)BL * NHEADS];
__device__ float    g_y   [(size_t)BL * DINNER];
// pre-split bf16 hi/lo operand planes
__device__ uint16_t g_uh  [(size_t)BL * DMODEL];
__device__ uint16_t g_ul  [(size_t)BL * DMODEL];
__device__ uint16_t g_ynh [(size_t)BL * DINNER];
__device__ uint16_t g_ynl [(size_t)BL * DINNER];
__device__ uint16_t g_wih [(size_t)DINPROJ * DMODEL];
__device__ uint16_t g_wil [(size_t)DINPROJ * DMODEL];
__device__ uint16_t g_woh [(size_t)DMODEL * DINNER];
__device__ uint16_t g_wol [(size_t)DMODEL * DINNER];
// scan pre-split planes
__device__ uint16_t g_bcsh[(size_t)BL * 128];                       // [t][B64|C64] hi
__device__ uint16_t g_bcsl[(size_t)BL * 128];
__device__ uint16_t g_bth [(size_t)BATCH * NCHUNK * 64 * 64];       // B^T [bc][n][t] hi
__device__ uint16_t g_btl [(size_t)BATCH * NCHUNK * 64 * 64];
__device__ uint16_t g_hch [(size_t)BATCH * NHEADS * NCHUNK * 4096]; // carry [p][n] hi
__device__ uint16_t g_hcl [(size_t)BATCH * NHEADS * NCHUNK * 4096];

// ---------------- helpers ---------------------------------------------------
__device__ __forceinline__ uint32_t smem_u32(const void* p) {
    uint32_t a;
    asm("{ .reg .u64 t; cvta.to.shared.u64 t, %1; cvt.u32.u64 %0, t; }"
        : "=r"(a) : "l"(p));
    return a;
}
// pack two f32 -> bf16x2 (first arg in LOW half)
__device__ __forceinline__ uint32_t packbf(float lo, float hi) {
    uint32_t r;
    asm("cvt.rn.bf16x2.f32 %0, %1, %2;" : "=r"(r) : "f"(hi), "f"(lo));
    return r;
}
// split float4 -> hi uint2 / lo uint2 (bf16x2 pairs)
__device__ __forceinline__ void split4(float4 v, uint2& hi, uint2& lo) {
    uint32_t h01 = packbf(v.x, v.y);
    uint32_t h23 = packbf(v.z, v.w);
    float rx = v.x - __uint_as_float(h01 << 16);
    float ry = v.y - __uint_as_float(h01 & 0xffff0000u);
    float rz = v.z - __uint_as_float(h23 << 16);
    float rw = v.w - __uint_as_float(h23 & 0xffff0000u);
    hi = make_uint2(h01, h23);
    lo = make_uint2(packbf(rx, ry), packbf(rz, rw));
}
__device__ __forceinline__ void split2(float a, float b, uint32_t& hi, uint32_t& lo) {
    hi = packbf(a, b);
    float ra = a - __uint_as_float(hi << 16);
    float rb = b - __uint_as_float(hi & 0xffff0000u);
    lo = packbf(ra, rb);
}

#define MMA_BF16(d, a, b0, b1) \
    asm volatile("mma.sync.aligned.m16n8k16.row.col.f32.bf16.bf16.f32 " \
        "{%0,%1,%2,%3}, {%4,%5,%6,%7}, {%8,%9}, {%0,%1,%2,%3};" \
        : "+f"((d)[0]), "+f"((d)[1]), "+f"((d)[2]), "+f"((d)[3]) \
        : "r"((a)[0]), "r"((a)[1]), "r"((a)[2]), "r"((a)[3]), \
          "r"(b0), "r"(b1))

#define LDSM_X4(r, addr) \
    asm volatile("ldmatrix.sync.aligned.m8n8.x4.shared.b16 {%0,%1,%2,%3}, [%4];" \
        : "=r"((r)[0]), "=r"((r)[1]), "=r"((r)[2]), "=r"((r)[3]) : "r"(addr))

#define CP_ASYNC16(dst, src) \
    asm volatile("cp.async.ca.shared.global [%0], [%1], 16;" \
        :: "r"(dst), "l"(src) : "memory")
#define CP_ASYNC16_P(dst, src, nbytes) \
    asm volatile("cp.async.ca.shared.global [%0], [%1], 16, %2;" \
        :: "r"(dst), "l"(src), "r"(nbytes) : "memory")
#define CP_ASYNC4(dst, src) \
    asm volatile("cp.async.ca.shared.global [%0], [%1], 4;" \
        :: "r"(dst), "l"(src) : "memory")
#define CP_COMMIT() asm volatile("cp.async.commit_group;" ::: "memory")
#define CP_WAIT0()  asm volatile("cp.async.wait_group 0;" ::: "memory")
#define CP_WAIT1()  asm volatile("cp.async.wait_group 1;" ::: "memory")

// -------- weight split kernel: fp32 -> bf16 hi/lo ---------------------------
__global__ void __launch_bounds__(256) wsplit_kernel(const float* __restrict__ src,
                                                     uint16_t* __restrict__ dh,
                                                     uint16_t* __restrict__ dl,
                                                     int n4)
{
    int i = blockIdx.x * 256 + threadIdx.x;
    if (i < n4) {
        float4 v = ((const float4*)src)[i];
        uint2 hi, lo;
        split4(v, hi, lo);
        ((uint2*)dh)[i] = hi;
        ((uint2*)dl)[i] = lo;
    }
}

// =============== bf16x3 emulated-fp32 NT GEMM (cp.async + LDSM) ============
#define KT        32
#define RSU       20                       // row stride (uint32 pairs, 80 B)
#define PL_AHI    0
#define PL_ALO    2560
#define PL_BHI    5120
#define PL_BLO    7680
#define STAGE_U   10240                    // uint32 per stage
#define SMEM_DYN  (2 * STAGE_U * 4)        // 81920 bytes

template<int N, int K, bool SECOND>
__global__ void __launch_bounds__(256, 2) gemm_tc(const float* __restrict__ resid,
                                                  float* __restrict__ outp)
{
    extern __shared__ uint32_t smu[];
    const uint16_t* __restrict__ Ah = SECOND ? g_ynh : g_uh;
    const uint16_t* __restrict__ Al = SECOND ? g_ynl : g_ul;
    const uint16_t* __restrict__ Wh = SECOND ? g_woh : g_wih;
    const uint16_t* __restrict__ Wl = SECOND ? g_wol : g_wil;
    float* __restrict__ Cptr        = SECOND ? outp : g_zx;

    int tid = threadIdx.x;
    int wid = tid >> 5, lane = tid & 31;
    int bm = blockIdx.y, bn = blockIdx.x;

    uint32_t sb = smem_u32(smu);

    int rA = tid >> 2, cA = (tid & 3) * 16;       // row 0..63, byte chunk
    const int NKT = K / KT;
    auto issue = [&](int kt) {
        if (kt < NKT) {
            uint32_t dst = sb + (uint32_t)(kt & 1) * (STAGE_U * 4);
            #pragma unroll
            for (int i = 0; i < 2; i++) {
                int row = rA + i * 64;
                uint32_t so = (uint32_t)(row * (RSU * 4)) + cA;
                size_t ao = (size_t)(bm * 128 + row) * K + kt * KT + (cA >> 1);
                CP_ASYNC16(dst + PL_AHI * 4 + so, Ah + ao);
                CP_ASYNC16(dst + PL_ALO * 4 + so, Al + ao);
                int nrow = bn * 128 + row;
                int nb = (nrow < N) ? 16 : 0;
                size_t bo = (size_t)nrow * K + kt * KT + (cA >> 1);
                CP_ASYNC16_P(dst + PL_BHI * 4 + so, Wh + bo, nb);
                CP_ASYNC16_P(dst + PL_BLO * 4 + so, Wl + bo, nb);
            }
        }
        CP_COMMIT();
    };

    int wm = wid >> 1, wn = wid & 1;
    int g = lane >> 2, t4 = lane & 3;

    uint32_t aoff = (uint32_t)(((wm * 32 + (lane & 15)) * RSU + 4 * (lane >> 4)) * 4);
    uint32_t boff = (uint32_t)(((wn * 64 + 8 * (lane >> 4) + (lane & 7)) * RSU
                                + 4 * ((lane >> 3) & 1)) * 4);

    float d[2][8][4];
    #pragma unroll
    for (int mt = 0; mt < 2; mt++)
        #pragma unroll
        for (int nt = 0; nt < 8; nt++)
            #pragma unroll
            for (int j = 0; j < 4; j++) d[mt][nt][j] = 0.f;

    issue(0);

    #pragma unroll 1
    for (int kt = 0; kt < NKT; ++kt) {
        issue(kt + 1);
        if (kt + 1 < NKT) CP_WAIT1(); else CP_WAIT0();
        __syncthreads();

        uint32_t base = sb + (uint32_t)(kt & 1) * (STAGE_U * 4);
        #pragma unroll
        for (int ks = 0; ks < 2; ks++) {
            uint32_t kby = (uint32_t)(ks * 8 * 4);
            uint32_t ah[2][4], al[2][4];
            #pragma unroll
            for (int mt = 0; mt < 2; mt++) {
                uint32_t aa = base + aoff + (uint32_t)(mt * 16 * RSU * 4) + kby;
                LDSM_X4(ah[mt], aa + PL_AHI * 4);
                LDSM_X4(al[mt], aa + PL_ALO * 4);
            }
            #pragma unroll
            for (int ntp = 0; ntp < 4; ntp++) {
                uint32_t ba = base + boff + (uint32_t)(ntp * 16 * RSU * 4) + kby;
                uint32_t bh[4], bl[4];
                LDSM_X4(bh, ba + PL_BHI * 4);
                LDSM_X4(bl, ba + PL_BLO * 4);
                #pragma unroll
                for (int mt = 0; mt < 2; mt++) {
                    MMA_BF16(d[mt][2*ntp],   ah[mt], bh[0], bh[1]);
                    MMA_BF16(d[mt][2*ntp],   ah[mt], bl[0], bl[1]);
                    MMA_BF16(d[mt][2*ntp],   al[mt], bh[0], bh[1]);
                    MMA_BF16(d[mt][2*ntp+1], ah[mt], bh[2], bh[3]);
                    MMA_BF16(d[mt][2*ntp+1], ah[mt], bl[2], bl[3]);
                    MMA_BF16(d[mt][2*ntp+1], al[mt], bh[2], bh[3]);
                }
            }
        }
        __syncthreads();
    }

    #pragma unroll
    for (int mt = 0; mt < 2; mt++) {
        int row = bm * 128 + wm * 32 + mt * 16 + g;
        #pragma unroll
        for (int nt = 0; nt < 8; nt++) {
            int col = bn * 128 + wn * 64 + nt * 8 + t4 * 2;
            if (col < N) {
                size_t i0 = (size_t)row * N + col;
                size_t i1 = (size_t)(row + 8) * N + col;
                float2 v0 = make_float2(d[mt][nt][0], d[mt][nt][1]);
                float2 v1 = make_float2(d[mt][nt][2], d[mt][nt][3]);
                if (SECOND) {
                    float2 r0v = *(const float2*)(resid + i0);
                    float2 r1v = *(const float2*)(resid + i1);
                    v0.x += r0v.x; v0.y += r0v.y;
                    v1.x += r1v.x; v1.y += r1v.y;
                }
                *(float2*)(Cptr + i0) = v0;
                *(float2*)(Cptr + i1) = v1;
            }
        }
    }
}

// ---------------- block reduction helper -----------------------------------
__device__ __forceinline__ float block_sum256(float v, float* sh) {
    #pragma unroll
    for (int o = 16; o; o >>= 1) v += __shfl_xor_sync(0xffffffffu, v, o);
    int lane = threadIdx.x & 31, wid = threadIdx.x >> 5;
    __syncthreads();
    if (lane == 0) sh[wid] = v;
    __syncthreads();
    float tt = 0.f;
    #pragma unroll
    for (int j = 0; j < 8; j++) tt += sh[j];
    return tt;
}

// ---------------- 1) LayerNorm (writes bf16 hi/lo planes) -------------------
__global__ void __launch_bounds__(256) ln_kernel(const float* __restrict__ x,
                                                 const float* __restrict__ w,
                                                 const float* __restrict__ bparm)
{
    __shared__ float sh[8];
    int row = blockIdx.x, tid = threadIdx.x;
    const float4* xr = (const float4*)(x + (size_t)row * DMODEL);
    float4 v = xr[tid];
    float s  = v.x + v.y + v.z + v.w;
    float mu = block_sum256(s, sh) * (1.f / DMODEL);
    float d0 = v.x - mu, d1 = v.y - mu, d2 = v.z - mu, d3 = v.w - mu;
    float vs = d0*d0 + d1*d1 + d2*d2 + d3*d3;
    float var = block_sum256(vs, sh) * (1.f / DMODEL);
    float inv = rsqrtf(var + 1e-5f);
    float4 wv = ((const float4*)w)[tid];
    float4 bv = ((const float4*)bparm)[tid];
    float4 o;
    o.x = d0 * inv * wv.x + bv.x;
    o.y = d1 * inv * wv.y + bv.y;
    o.z = d2 * inv * wv.z + bv.z;
    o.w = d3 * inv * wv.w + bv.w;
    uint2 hi, lo;
    split4(o, hi, lo);
    size_t idx = (size_t)row * DMODEL + tid * 4;
    *(uint2*)(g_uh + idx) = hi;
    *(uint2*)(g_ul + idx) = lo;
}

// ---------------- 3) rolling-window conv(4)+SiLU + fused dt + BC split ------
// Thread owns one channel for 16 consecutive rows; 3-tap history in regs.
// B/C channels (2048..2175) additionally write bf16 hi/lo straight planes.
__global__ void __launch_bounds__(256) conv_dt_kernel(const float* __restrict__ conv_w,
                                                      const float* __restrict__ conv_b,
                                                      const float* __restrict__ dt_bias)
{
    int c  = blockIdx.x * 256 + threadIdx.x;
    int i0 = blockIdx.y * 16;                 // first global row of tile
    int b  = i0 >> 12;
    int l0 = i0 & 4095;
    if (c < CONVDIM) {
        float w0 = conv_w[c*4+0], w1 = conv_w[c*4+1];
        float w2 = conv_w[c*4+2], w3 = conv_w[c*4+3];
        float bias = conv_b[c];
        bool isbc = (c >= DINNER);
        int bcc = c - DINNER;
        const float* col = g_zx + ((size_t)b << 12) * DINPROJ + DINNER + c;
        float xm3 = (l0 >= 3) ? col[(size_t)(l0-3) * DINPROJ] : 0.f;
        float xm2 = (l0 >= 2) ? col[(size_t)(l0-2) * DINPROJ] : 0.f;
        float xm1 = (l0 >= 1) ? col[(size_t)(l0-1) * DINPROJ] : 0.f;
        #pragma unroll
        for (int j = 0; j < 16; j++) {
            float x0 = col[(size_t)(l0 + j) * DINPROJ];
            float s = bias + xm3 * w0 + xm2 * w1 + xm1 * w2 + x0 * w3;
            s = s / (1.f + expf(-s));
            g_xbca[(size_t)(i0 + j) * CONVDIM + c] = s;
            if (isbc) {
                uint32_t hb = packbf(s, s);
                float l = s - __uint_as_float(hb << 16);
                uint32_t lb = packbf(l, l);
                size_t o = (size_t)(i0 + j) * 128 + bcc;
                g_bcsh[o] = (uint16_t)hb;
                g_bcsl[o] = (uint16_t)lb;
            }
            xm3 = xm2; xm2 = xm1; xm1 = x0;
        }
    } else if (c < CONVDIM + NHEADS) {
        int hh = c - CONVDIM;
        float bias = dt_bias[hh];
        const float* src = g_zx + (size_t)i0 * DINPROJ + (DINNER + CONVDIM) + hh;
        #pragma unroll
        for (int j = 0; j < 16; j++) {
            float v = src[(size_t)j * DINPROJ] + bias;
            g_dt[(size_t)(i0 + j) * NHEADS + hh] = (v > 20.f) ? v : log1pf(expf(v));
        }
    }
}

// ---------------- 3b) B transpose split: B^T [bc][n][t] ---------------------
__global__ void __launch_bounds__(256) btrans_kernel()
{
    __shared__ float sb[64][68];
    int bc = blockIdx.x;                  // b*NCHUNK + chunk (rows bc*64..+63)
    int tid = threadIdx.x;
    const float* src = g_xbca + (size_t)bc * 64 * CONVDIM + 2048;
    #pragma unroll
    for (int i = 0; i < 4; i++) {
        int idx = tid + i * 256;          // 1024 float4 (B region only)
        int t = idx >> 4, c4 = (idx & 15) * 4;
        *(float4*)&sb[t][c4] = *(const float4*)(src + (size_t)t * CONVDIM + c4);
    }
    __syncthreads();
    int n = tid >> 2, tg = (tid & 3) * 16;
    uint32_t hi[8], lo[8];
    #pragma unroll
    for (int j = 0; j < 8; j++)
        split2(sb[tg + 2*j][n], sb[tg + 2*j + 1][n], hi[j], lo[j]);
    size_t o = ((size_t)bc * 64 + n) * 64 + tg;
    *(uint4*)(g_bth + o)     = make_uint4(hi[0], hi[1], hi[2], hi[3]);
    *(uint4*)(g_bth + o + 8) = make_uint4(hi[4], hi[5], hi[6], hi[7]);
    *(uint4*)(g_btl + o)     = make_uint4(lo[0], lo[1], lo[2], lo[3]);
    *(uint4*)(g_btl + o + 8) = make_uint4(lo[4], lo[5], lo[6], lo[7]);
}

// -------- warp-0 inclusive scan of 64 s-values (dt*Ah) -> cum[64] ----------
__device__ __forceinline__ void scan64(const float* dtv, float Ah, float* cum, int tid) {
    if (tid < 32) {
        float a = dtv[tid] * Ah;
        float b = dtv[32 + tid] * Ah;
        #pragma unroll
        for (int o = 1; o < 32; o <<= 1) {
            float ta = __shfl_up_sync(0xffffffffu, a, o);
            float tb = __shfl_up_sync(0xffffffffu, b, o);
            if (tid >= o) { a += ta; b += tb; }
        }
        float totA = __shfl_sync(0xffffffffu, a, 31);
        cum[tid]      = a;
        cum[32 + tid] = totA + b;
    }
}

// ---------------- 4a) S1: chunk-state pass (bf16x3 MMA, pre-split B^T) -----
#define S1_XF    0                          // fp32 X [64][68]
#define S1_BT    4352                       // B^T hi [32 n][36] u32
#define S1_BTLO  5504
#define S1_DT    6656
#define S1_BUF   6720                       // ring buffer (x2)
#define S1_XWT   13440                      // XWT hi [64 p][36] u32
#define S1_XWTLO 15744
#define S1_W     18048
#define S1_CUM   18112
#define S1_SMEMF 18176
#define S1_SMEMB (S1_SMEMF * 4)             // 72704 bytes

__global__ void __launch_bounds__(256) s1_kernel(const float* __restrict__ A_log)
{
    extern __shared__ float sm[];
    uint32_t* su = (uint32_t*)sm;
    int bx = blockIdx.x;
    int b = bx >> 6, h = (bx >> 1) & 31, nh = bx & 1;
    int tid = threadIdx.x;
    int wid = tid >> 5, lane = tid & 31;
    int wm = wid & 1, wn = wid >> 1;        // n-tile (16), p-quarter (16)
    int g = lane >> 2, t4 = lane & 3;
    float Ah = -expf(A_log[h]);

    float* w   = sm + S1_W;
    float* cum = sm + S1_CUM;
    uint32_t sbase = smem_u32(sm);

    const float* base = g_xbca + (size_t)b * SEQLEN * CONVDIM;
    const float* dtb  = g_dt   + (size_t)b * SEQLEN * NHEADS + h;

    auto issue = [&](int c) {
        if (c < NCHUNK) {
            uint32_t dst = sbase + (uint32_t)(c & 1) * (S1_BUF * 4);
            const float* rowb = base + (size_t)c * CHUNK * CONVDIM;
            #pragma unroll
            for (int i = 0; i < 4; i++) {              // X fp32: 1024 f4
                int f4 = tid + i * 256;
                int t = f4 >> 4, j = (f4 & 15) * 4;
                CP_ASYNC16(dst + (uint32_t)(t * 68 + j) * 4,
                           rowb + (size_t)t * CONVDIM + h * 64 + j);
            }
            {                                          // B^T planes
                int n = tid >> 3, ch = tid & 7;
                size_t src = ((size_t)(b * NCHUNK + c) * 64 + nh * 32 + n) * 64 + ch * 8;
                uint32_t so = (uint32_t)(n * 36 + ch * 4) * 4;
                CP_ASYNC16(dst + S1_BT * 4 + so, g_bth + src);
                CP_ASYNC16(dst + S1_BTLO * 4 + so, g_btl + src);
            }
            if (tid < 64)
                CP_ASYNC4(dst + S1_DT * 4 + tid * 4,
                          dtb + (size_t)(c * CHUNK + tid) * NHEADS);
        }
        CP_COMMIT();
    };

    float d0[4] = {0.f, 0.f, 0.f, 0.f};
    float d1[4] = {0.f, 0.f, 0.f, 0.f};

    issue(0); issue(1);

    for (int c = 0; c < NCHUNK; c++) {
        CP_WAIT1();
        __syncthreads();
        float* S = sm + (c & 1) * S1_BUF;
        uint32_t* SU = su + (c & 1) * S1_BUF;

        scan64(S + S1_DT, Ah, cum, tid);
        __syncthreads();

        float cl = cum[63];
        float E  = expf(cl);
        if (tid < 64) w[tid] = expf(cl - cum[tid]) * S[S1_DT + tid];

        // carry store (state at chunk start) as bf16 hi/lo planes [p][n]
        {
            size_t hcb = (((size_t)(b * 32 + h)) * NCHUNK + c) * 4096;
            int n0 = nh * 32 + wm * 16 + g;
            int p0 = wn * 16 + 2 * t4;
            auto stbf = [&](int p, int n, float v) {
                uint32_t hb = packbf(v, v);
                float l = v - __uint_as_float(hb << 16);
                uint32_t lb = packbf(l, l);
                size_t a = hcb + (size_t)p * 64 + n;
                g_hch[a] = (uint16_t)hb;
                g_hcl[a] = (uint16_t)lb;
            };
            stbf(p0,     n0,     d0[0]); stbf(p0 + 1, n0,     d0[1]);
            stbf(p0,     n0 + 8, d0[2]); stbf(p0 + 1, n0 + 8, d0[3]);
            stbf(p0 + 8, n0,     d1[0]); stbf(p0 + 9, n0,     d1[1]);
            stbf(p0 + 8, n0 + 8, d1[2]); stbf(p0 + 9, n0 + 8, d1[3]);
        }
        #pragma unroll
        for (int j = 0; j < 4; j++) { d0[j] *= E; d1[j] *= E; }
        __syncthreads();                      // w ready; prev XWT reads done

        // build XWT planes: [p][t-pairs], value = w_t * X[t][p]
        {
            int p = tid & 63, tq = tid >> 6;
            uint32_t hi[8], lo[8];
            #pragma unroll
            for (int q = 0; q < 8; q++) {
                int t0 = tq * 16 + 2 * q;
                float a = S[t0 * 68 + p] * w[t0];
                float bb = S[(t0 + 1) * 68 + p] * w[t0 + 1];
                split2(a, bb, hi[q], lo[q]);
            }
            int o = S1_XWT + p * 36 + tq * 8;
            *(uint4*)&su[o]            = make_uint4(hi[0], hi[1], hi[2], hi[3]);
            *(uint4*)&su[o + 4]        = make_uint4(hi[4], hi[5], hi[6], hi[7]);
            *(uint4*)&su[o + 2304]     = make_uint4(lo[0], lo[1], lo[2], lo[3]);
            *(uint4*)&su[o + 2304 + 4] = make_uint4(lo[4], lo[5], lo[6], lo[7]);
        }
        __syncthreads();                      // XWT ready

        // MMA: dd[pb] += B^T(n,t) x XWT(p,t)^T
        const uint32_t* BT = SU + S1_BT;
        #pragma unroll
        for (int kc = 0; kc < 4; kc++) {
            int o0 = (wm * 16 + g) * 36 + kc * 8 + t4;
            int o1 = o0 + 8 * 36;
            uint32_t ah[4], al[4];
            ah[0] = BT[o0];     ah[1] = BT[o1];
            ah[2] = BT[o0 + 4]; ah[3] = BT[o1 + 4];
            al[0] = BT[1152 + o0];     al[1] = BT[1152 + o1];
            al[2] = BT[1152 + o0 + 4]; al[3] = BT[1152 + o1 + 4];
            #pragma unroll
            for (int pb = 0; pb < 2; pb++) {
                int pr = S1_XWT + (wn * 16 + pb * 8 + g) * 36 + kc * 8 + t4;
                uint32_t bh0 = su[pr], bh1 = su[pr + 4];
                uint32_t bl0 = su[pr + 2304], bl1 = su[pr + 2304 + 4];
                float* dd = pb ? d1 : d0;
                MMA_BF16(dd, ah, bh0, bh1);
                MMA_BF16(dd, ah, bl0, bl1);
                MMA_BF16(dd, al, bh0, bh1);
            }
        }
        __syncthreads();                      // reads done before restage
        issue(c + 2);
    }
}

// ---------------- 4b) S2: per-chunk parallel y (bf16x3 MMA, pre-split) ------
#define P_A     0          // C hi (later G hi)
#define P_ALO   2304
#define P_B     4608
#define P_BLO   6912
#define P_C2    9216
#define P_C2LO  11520
#define P_XT    13824
#define P_XTLO  16128
#define P_HT    18432
#define P_HTLO  20736
#define P_XF    23040      // fp32 X tile [64][68]
#define P_DT2   27392
#define P_CUM2  27456
#define S2N_U   27520
#define S2N_B   (S2N_U * 4)   // 110080 bytes

__global__ void __launch_bounds__(256) s2_kernel(const float* __restrict__ A_log,
                                                 const float* __restrict__ Dp)
{
    extern __shared__ uint32_t su[];
    float* sf = (float*)su;
    int bx = blockIdx.x;
    int c = bx & 63, h = (bx >> 6) & 31, b = bx >> 11;
    int tid = threadIdx.x;
    int wid = tid >> 5, lane = tid & 31;
    int wm = wid >> 1, wn = wid & 1;        // 4x2 warp grid, warp tile 16x32
    int g = lane >> 2, t4 = lane & 3;
    float Ah = -expf(A_log[h]);
    float Dh = Dp[h];

    uint32_t sb = smem_u32(su);
    const float* rowb = g_xbca + ((size_t)b * SEQLEN + c * 64) * CONVDIM;

    // ---- async loads: C/B planes, HT planes, X fp32, dt --------------------
    {
        int r = tid >> 2, q = tid & 3;
        size_t ib = ((size_t)(b * SEQLEN + c * 64 + r)) * 128;
        size_t hb = (((size_t)(b * 32 + h)) * NCHUNK + c) * 4096 + (size_t)r * 64;
        #pragma unroll
        for (int k = 0; k < 2; k++) {
            int ch = q * 2 + k;
            uint32_t so = (uint32_t)(r * 36 + ch * 4) * 4;
            CP_ASYNC16(sb + P_A * 4 + so,    g_bcsh + ib + 64 + ch * 8);
            CP_ASYNC16(sb + P_ALO * 4 + so,  g_bcsl + ib + 64 + ch * 8);
            CP_ASYNC16(sb + P_B * 4 + so,    g_bcsh + ib + ch * 8);
            CP_ASYNC16(sb + P_BLO * 4 + so,  g_bcsl + ib + ch * 8);
            CP_ASYNC16(sb + P_HT * 4 + so,   g_hch + hb + ch * 8);
            CP_ASYNC16(sb + P_HTLO * 4 + so, g_hcl + hb + ch * 8);
        }
        #pragma unroll
        for (int i = 0; i < 4; i++) {
            int f4 = tid + i * 256;
            int t = f4 >> 4, j = (f4 & 15) * 4;
            CP_ASYNC16(sb + (uint32_t)(P_XF + t * 68 + j) * 4,
                       rowb + (size_t)t * CONVDIM + h * 64 + j);
        }
        if (tid < 64)
            CP_ASYNC4(sb + (uint32_t)(P_DT2 + tid) * 4,
                      g_dt + ((size_t)b * SEQLEN + c * 64 + tid) * NHEADS + h);
        CP_COMMIT();
    }

    // fp32 C rows for C2 (independent regular loads)
    int r = tid >> 2;
    int cg = (tid & 3) * 16;
    float4 cre[4];
    #pragma unroll
    for (int i = 0; i < 4; i++)
        cre[i] = *(const float4*)(rowb + (size_t)r * CONVDIM + 2112 + cg + 4 * i);

    CP_WAIT0();
    __syncthreads();

    scan64(sf + P_DT2, Ah, sf + P_CUM2, tid);
    __syncthreads();

    // ---- C2 = Et*C planes, XT planes ---------------------------------------
    {
        float Et = expf(sf[P_CUM2 + r]);
        #pragma unroll
        for (int i = 0; i < 4; i++) {
            float4 v = cre[i];
            v.x *= Et; v.y *= Et; v.z *= Et; v.w *= Et;
            uint2 hi, lo;
            split4(v, hi, lo);
            int col = cg + 4 * i;
            *(uint2*)&su[P_C2 + r * 36 + col / 2]          = hi;
            *(uint2*)&su[P_C2 + 2304 + r * 36 + col / 2]   = lo;
        }
    }
    {
        int p = tid & 63, tq = tid >> 6;
        uint32_t hi[8], lo[8];
        #pragma unroll
        for (int q = 0; q < 8; q++) {
            int t0 = tq * 16 + 2 * q;
            split2(sf[P_XF + t0 * 68 + p], sf[P_XF + (t0 + 1) * 68 + p], hi[q], lo[q]);
        }
        int o = P_XT + p * 36 + tq * 8;
        *(uint4*)&su[o]            = make_uint4(hi[0], hi[1], hi[2], hi[3]);
        *(uint4*)&su[o + 4]        = make_uint4(hi[4], hi[5], hi[6], hi[7]);
        *(uint4*)&su[o + 2304]     = make_uint4(lo[0], lo[1], lo[2], lo[3]);
        *(uint4*)&su[o + 2304 + 4] = make_uint4(lo[4], lo[5], lo[6], lo[7]);
    }
    __syncthreads();

    auto mm = [&](uint32_t offA, uint32_t offB, float (*dd)[4]) {
        #pragma unroll
        for (int ks = 0; ks < 4; ks++) {
            int kb = ks * 8;
            uint32_t ah[4], al[4];
            int o0 = (wm * 16 + g) * 36 + kb + t4;
            int o1 = o0 + 8 * 36;
            ah[0] = su[offA + o0];     ah[1] = su[offA + o1];
            ah[2] = su[offA + o0 + 4]; ah[3] = su[offA + o1 + 4];
            al[0] = su[offA + 2304 + o0];     al[1] = su[offA + 2304 + o1];
            al[2] = su[offA + 2304 + o0 + 4]; al[3] = su[offA + 2304 + o1 + 4];
            #pragma unroll
            for (int nt = 0; nt < 4; nt++) {
                int ob = (wn * 32 + nt * 8 + g) * 36 + kb + t4;
                uint32_t bh0 = su[offB + ob], bh1 = su[offB + ob + 4];
                uint32_t bl0 = su[offB + 2304 + ob], bl1 = su[offB + 2304 + ob + 4];
                MMA_BF16(dd[nt], ah, bh0, bh1);
                MMA_BF16(dd[nt], ah, bl0, bl1);
                MMA_BF16(dd[nt], al, bh0, bh1);
            }
        }
    };

    float d[4][4];
    #pragma unroll
    for (int nt = 0; nt < 4; nt++)
        #pragma unroll
        for (int j = 0; j < 4; j++) d[nt][j] = 0.f;
    // causal skip: warps whose t-range lies entirely below s-range have G==0
    if (wm * 16 + 15 >= wn * 32)
        mm(P_A, P_B, d);

    int t0 = wm * 16 + g, t1 = t0 + 8;
    float ct0 = sf[P_CUM2 + t0], ct1 = sf[P_CUM2 + t1];
    float gv[4][4];
    #pragma unroll
    for (int nt = 0; nt < 4; nt++) {
        int s0 = wn * 32 + nt * 8 + 2 * t4, s1 = s0 + 1;
        float cs0 = sf[P_CUM2 + s0], cs1 = sf[P_CUM2 + s1];
        float w0 = sf[P_DT2 + s0],  w1 = sf[P_DT2 + s1];
        gv[nt][0] = (s0 <= t0) ? d[nt][0] * expf(ct0 - cs0) * w0 : 0.f;
        gv[nt][1] = (s1 <= t0) ? d[nt][1] * expf(ct0 - cs1) * w1 : 0.f;
        gv[nt][2] = (s0 <= t1) ? d[nt][2] * expf(ct1 - cs0) * w0 : 0.f;
        gv[nt][3] = (s1 <= t1) ? d[nt][3] * expf(ct1 - cs1) * w1 : 0.f;
    }
    __syncthreads();

    #pragma unroll
    for (int nt = 0; nt < 4; nt++) {
        int pi = wn * 16 + nt * 4 + t4;
        uint32_t h01, l01, h23, l23;
        split2(gv[nt][0], gv[nt][1], h01, l01);
        split2(gv[nt][2], gv[nt][3], h23, l23);
        su[P_A   + t0 * 36 + pi] = h01;
        su[P_ALO + t0 * 36 + pi] = l01;
        su[P_A   + t1 * 36 + pi] = h23;
        su[P_ALO + t1 * 36 + pi] = l23;
    }
    __syncthreads();

    #pragma unroll
    for (int nt = 0; nt < 4; nt++)
        #pragma unroll
        for (int j = 0; j < 4; j++) d[nt][j] = 0.f;
    mm(P_A, P_XT, d);
    mm(P_C2, P_HT, d);

    float* yo = g_y + ((size_t)b * SEQLEN + c * 64) * DINNER + h * 64;
    #pragma unroll
    for (int nt = 0; nt < 4; nt++) {
        int p0 = wn * 32 + nt * 8 + 2 * t4;
        float2 x0 = *(const float2*)&sf[P_XF + t0 * 68 + p0];
        float2 x1 = *(const float2*)&sf[P_XF + t1 * 68 + p0];
        float2 v0 = make_float2(d[nt][0] + Dh * x0.x, d[nt][1] + Dh * x0.y);
        float2 v1 = make_float2(d[nt][2] + Dh * x1.x, d[nt][3] + Dh * x1.y);
        *(float2*)&yo[(size_t)t0 * DINNER + p0] = v0;
        *(float2*)&yo[(size_t)t1 * DINNER + p0] = v1;
    }
}

// ---------------- 5) gate + RMSNorm (writes bf16 hi/lo planes) --------------
__global__ void __launch_bounds__(256) gate_rms_kernel(const float* __restrict__ norm_w)
{
    __shared__ float sh[8];
    int row = blockIdx.x, tid = threadIdx.x;
    const float4* y4 = (const float4*)(g_y  + (size_t)row * DINNER);
    const float4* z4 = (const float4*)(g_zx + (size_t)row * DINPROJ);
    float4 a0 = y4[tid], a1 = y4[tid + 256];
    float4 z0 = z4[tid], z1 = z4[tid + 256];
    float g[8];
    g[0] = a0.x * (z0.x / (1.f + expf(-z0.x)));
    g[1] = a0.y * (z0.y / (1.f + expf(-z0.y)));
    g[2] = a0.z * (z0.z / (1.f + expf(-z0.z)));
    g[3] = a0.w * (z0.w / (1.f + expf(-z0.w)));
    g[4] = a1.x * (z1.x / (1.f + expf(-z1.x)));
    g[5] = a1.y * (z1.y / (1.f + expf(-z1.y)));
    g[6] = a1.z * (z1.z / (1.f + expf(-z1.z)));
    g[7] = a1.w * (z1.w / (1.f + expf(-z1.w)));
    float ss = 0.f;
    #pragma unroll
    for (int j = 0; j < 8; j++) ss += g[j] * g[j];
    float tot = block_sum256(ss, sh);
    float inv = rsqrtf(tot * (1.f / DINNER) + 1e-5f);
    float4 w0 = ((const float4*)norm_w)[tid];
    float4 w1 = ((const float4*)norm_w)[tid + 256];
    float4 o0, o1;
    o0.x = g[0] * inv * w0.x; o0.y = g[1] * inv * w0.y;
    o0.z = g[2] * inv * w0.z; o0.w = g[3] * inv * w0.w;
    o1.x = g[4] * inv * w1.x; o1.y = g[5] * inv * w1.y;
    o1.z = g[6] * inv * w1.z; o1.w = g[7] * inv * w1.w;
    uint2 hi, lo;
    size_t idx = (size_t)row * DINNER + tid * 4;
    split4(o0, hi, lo);
    *(uint2*)(g_ynh + idx) = hi;
    *(uint2*)(g_ynl + idx) = lo;
    split4(o1, hi, lo);
    *(uint2*)(g_ynh + idx + 1024) = hi;
    *(uint2*)(g_ynl + idx + 1024) = lo;
}

// ---------------- launcher -------------------------------------------------
extern "C" void kernel_launch(void* const* d_in, const int* in_sizes, int n_in,
                              void* d_out, int out_size)
{
    const float* x       = (const float*)d_in[0];
    const float* ln_w    = (const float*)d_in[1];
    const float* ln_b    = (const float*)d_in[2];
    const float* W_in    = (const float*)d_in[3];
    const float* conv_w  = (const float*)d_in[4];
    const float* conv_b  = (const float*)d_in[5];
    const float* dt_bias = (const float*)d_in[6];
    const float* A_log   = (const float*)d_in[7];
    const float* Dp      = (const float*)d_in[8];
    const float* norm_w  = (const float*)d_in[9];
    const float* W_out   = (const float*)d_in[10];
    float* out = (float*)d_out;

    cudaFuncSetAttribute(gemm_tc<DINPROJ, DMODEL, false>,
                         cudaFuncAttributeMaxDynamicSharedMemorySize, SMEM_DYN);
    cudaFuncSetAttribute(gemm_tc<DMODEL, DINNER, true>,
                         cudaFuncAttributeMaxDynamicSharedMemorySize, SMEM_DYN);
    cudaFuncSetAttribute(s1_kernel,
                         cudaFuncAttributeMaxDynamicSharedMemorySize, S1_SMEMB);
    cudaFuncSetAttribute(s2_kernel,
                         cudaFuncAttributeMaxDynamicSharedMemorySize, S2N_B);

    uint16_t *wih, *wil, *woh, *wol;
    cudaGetSymbolAddress((void**)&wih, g_wih);
    cudaGetSymbolAddress((void**)&wil, g_wil);
    cudaGetSymbolAddress((void**)&woh, g_woh);
    cudaGetSymbolAddress((void**)&wol, g_wol);

    wsplit_kernel<<<(DINPROJ * DMODEL / 4 + 255) / 256, 256>>>(W_in, wih, wil,
                                                               DINPROJ * DMODEL / 4); // 1
    ln_kernel<<<BL, 256>>>(x, ln_w, ln_b);                          // 2

    gemm_tc<DINPROJ, DMODEL, false>                                 // 3
        <<<dim3((DINPROJ + 127) / 128, BL / 128), 256, SMEM_DYN>>>(nullptr, nullptr);

    conv_dt_kernel<<<dim3(9, BL / 16), 256>>>(conv_w, conv_b, dt_bias); // 4 <- ncu window

    wsplit_kernel<<<(DMODEL * DINNER / 4 + 255) / 256, 256>>>(W_out, woh, wol,
                                                              DMODEL * DINNER / 4);   // 5

    btrans_kernel<<<BATCH * NCHUNK, 256>>>();                       // 6

    s1_kernel<<<BATCH * NHEADS * 2, 256, S1_SMEMB>>>(A_log);        // 7

    s2_kernel<<<BATCH * NHEADS * NCHUNK, 256, S2N_B>>>(A_log, Dp);  // 8

    gate_rms_kernel<<<BL, 256>>>(norm_w);                           // 9

    gemm_tc<DMODEL, DINNER, true>                                   // 10
        <<<dim3(DMODEL / 128, BL / 128), 256, SMEM_DYN>>>(x, out);
}

// round 17
// speedup vs baseline: 1.0728x; 1.0003x over previous
#include <cuda_runtime.h>
#include <cstdint>
#include <math.h>

#define BATCH   2
#define SEQLEN  4096
#define DMODEL  1024
#define DINNER  2048
#define NHEADS  32
#define HEADDIM 64
#define DSTATE  64
#define CONVDIM 2176            // DINNER + 2*DSTATE
#define DINPROJ 4256            // 2*DINNER + 2*DSTATE + NHEADS
#define BL      8192            // BATCH*SEQLEN
#define CHUNK   64
#define NCHUNK  (SEQLEN / CHUNK)   // 64

// ---------------- scratch (static device globals: no allocations) ----------
__device__ float    g_zx  [(size_t)BL * DINPROJ];
__device__ float    g_xbca[(size_t)BL * CONVDIM];
__device__ float    g_dt  [(size_t)BL * NHEADS];
__device__ float    g_y   [(size_t)BL * DINNER];
// pre-split bf16 hi/lo operand planes
__device__ uint16_t g_uh  [(size_t)BL * DMODEL];
__device__ uint16_t g_ul  [(size_t)BL * DMODEL];
__device__ uint16_t g_ynh [(size_t)BL * DINNER];
__device__ uint16_t g_ynl [(size_t)BL * DINNER];
__device__ uint16_t g_wih [(size_t)DINPROJ * DMODEL];
__device__ uint16_t g_wil [(size_t)DINPROJ * DMODEL];
__device__ uint16_t g_woh [(size_t)DMODEL * DINNER];
__device__ uint16_t g_wol [(size_t)DMODEL * DINNER];
// scan pre-split planes
__device__ uint16_t g_bcsh[(size_t)BL * 128];                       // [t][B64|C64] hi
__device__ uint16_t g_bcsl[(size_t)BL * 128];
__device__ uint16_t g_bth [(size_t)BATCH * NCHUNK * 64 * 64];       // B^T [bc][n][t] hi
__device__ uint16_t g_btl [(size_t)BATCH * NCHUNK * 64 * 64];
__device__ uint16_t g_hch [(size_t)BATCH * NHEADS * NCHUNK * 4096]; // carry [p][n] hi
__device__ uint16_t g_hcl [(size_t)BATCH * NHEADS * NCHUNK * 4096];

// ---------------- helpers ---------------------------------------------------
__device__ __forceinline__ uint32_t smem_u32(const void* p) {
    uint32_t a;
    asm("{ .reg .u64 t; cvta.to.shared.u64 t, %1; cvt.u32.u64 %0, t; }"
        : "=r"(a) : "l"(p));
    return a;
}
// pack two f32 -> bf16x2 (first arg in LOW half)
__device__ __forceinline__ uint32_t packbf(float lo, float hi) {
    uint32_t r;
    asm("cvt.rn.bf16x2.f32 %0, %1, %2;" : "=r"(r) : "f"(hi), "f"(lo));
    return r;
}
// split float4 -> hi uint2 / lo uint2 (bf16x2 pairs)
__device__ __forceinline__ void split4(float4 v, uint2& hi, uint2& lo) {
    uint32_t h01 = packbf(v.x, v.y);
    uint32_t h23 = packbf(v.z, v.w);
    float rx = v.x - __uint_as_float(h01 << 16);
    float ry = v.y - __uint_as_float(h01 & 0xffff0000u);
    float rz = v.z - __uint_as_float(h23 << 16);
    float rw = v.w - __uint_as_float(h23 & 0xffff0000u);
    hi = make_uint2(h01, h23);
    lo = make_uint2(packbf(rx, ry), packbf(rz, rw));
}
__device__ __forceinline__ void split2(float a, float b, uint32_t& hi, uint32_t& lo) {
    hi = packbf(a, b);
    float ra = a - __uint_as_float(hi << 16);
    float rb = b - __uint_as_float(hi & 0xffff0000u);
    lo = packbf(ra, rb);
}

#define MMA_BF16(d, a, b0, b1) \
    asm volatile("mma.sync.aligned.m16n8k16.row.col.f32.bf16.bf16.f32 " \
        "{%0,%1,%2,%3}, {%4,%5,%6,%7}, {%8,%9}, {%0,%1,%2,%3};" \
        : "+f"((d)[0]), "+f"((d)[1]), "+f"((d)[2]), "+f"((d)[3]) \
        : "r"((a)[0]), "r"((a)[1]), "r"((a)[2]), "r"((a)[3]), \
          "r"(b0), "r"(b1))

#define LDSM_X4(r, addr) \
    asm volatile("ldmatrix.sync.aligned.m8n8.x4.shared.b16 {%0,%1,%2,%3}, [%4];" \
        : "=r"((r)[0]), "=r"((r)[1]), "=r"((r)[2]), "=r"((r)[3]) : "r"(addr))

#define CP_ASYNC16(dst, src) \
    asm volatile("cp.async.ca.shared.global [%0], [%1], 16;" \
        :: "r"(dst), "l"(src) : "memory")
#define CP_ASYNC16_P(dst, src, nbytes) \
    asm volatile("cp.async.ca.shared.global [%0], [%1], 16, %2;" \
        :: "r"(dst), "l"(src), "r"(nbytes) : "memory")
#define CP_ASYNC4(dst, src) \
    asm volatile("cp.async.ca.shared.global [%0], [%1], 4;" \
        :: "r"(dst), "l"(src) : "memory")
#define CP_COMMIT() asm volatile("cp.async.commit_group;" ::: "memory")
#define CP_WAIT0()  asm volatile("cp.async.wait_group 0;" ::: "memory")
#define CP_WAIT1()  asm volatile("cp.async.wait_group 1;" ::: "memory")

// -------- weight split kernel: fp32 -> bf16 hi/lo ---------------------------
__global__ void __launch_bounds__(256) wsplit_kernel(const float* __restrict__ src,
                                                     uint16_t* __restrict__ dh,
                                                     uint16_t* __restrict__ dl,
                                                     int n4)
{
    int i = blockIdx.x * 256 + threadIdx.x;
    if (i < n4) {
        float4 v = ((const float4*)src)[i];
        uint2 hi, lo;
        split4(v, hi, lo);
        ((uint2*)dh)[i] = hi;
        ((uint2*)dl)[i] = lo;
    }
}

// =============== bf16x3 emulated-fp32 NT GEMM (cp.async + LDSM) ============
#define KT        32
#define RSU       20                       // row stride (uint32 pairs, 80 B)
#define PL_AHI    0
#define PL_ALO    2560
#define PL_BHI    5120
#define PL_BLO    7680
#define STAGE_U   10240                    // uint32 per stage
#define SMEM_DYN  (2 * STAGE_U * 4)        // 81920 bytes

template<int N, int K, bool SECOND>
__global__ void __launch_bounds__(256, 2) gemm_tc(const float* __restrict__ resid,
                                                  float* __restrict__ outp)
{
    extern __shared__ uint32_t smu[];
    const uint16_t* __restrict__ Ah = SECOND ? g_ynh : g_uh;
    const uint16_t* __restrict__ Al = SECOND ? g_ynl : g_ul;
    const uint16_t* __restrict__ Wh = SECOND ? g_woh : g_wih;
    const uint16_t* __restrict__ Wl = SECOND ? g_wol : g_wil;
    float* __restrict__ Cptr        = SECOND ? outp : g_zx;

    int tid = threadIdx.x;
    int wid = tid >> 5, lane = tid & 31;
    int bm = blockIdx.y, bn = blockIdx.x;

    uint32_t sb = smem_u32(smu);

    int rA = tid >> 2, cA = (tid & 3) * 16;       // row 0..63, byte chunk
    const int NKT = K / KT;
    auto issue = [&](int kt) {
        if (kt < NKT) {
            uint32_t dst = sb + (uint32_t)(kt & 1) * (STAGE_U * 4);
            #pragma unroll
            for (int i = 0; i < 2; i++) {
                int row = rA + i * 64;
                uint32_t so = (uint32_t)(row * (RSU * 4)) + cA;
                size_t ao = (size_t)(bm * 128 + row) * K + kt * KT + (cA >> 1);
                CP_ASYNC16(dst + PL_AHI * 4 + so, Ah + ao);
                CP_ASYNC16(dst + PL_ALO * 4 + so, Al + ao);
                int nrow = bn * 128 + row;
                int nb = (nrow < N) ? 16 : 0;
                size_t bo = (size_t)nrow * K + kt * KT + (cA >> 1);
                CP_ASYNC16_P(dst + PL_BHI * 4 + so, Wh + bo, nb);
                CP_ASYNC16_P(dst + PL_BLO * 4 + so, Wl + bo, nb);
            }
        }
        CP_COMMIT();
    };

    int wm = wid >> 1, wn = wid & 1;
    int g = lane >> 2, t4 = lane & 3;

    uint32_t aoff = (uint32_t)(((wm * 32 + (lane & 15)) * RSU + 4 * (lane >> 4)) * 4);
    uint32_t boff = (uint32_t)(((wn * 64 + 8 * (lane >> 4) + (lane & 7)) * RSU
                                + 4 * ((lane >> 3) & 1)) * 4);

    float d[2][8][4];
    #pragma unroll
    for (int mt = 0; mt < 2; mt++)
        #pragma unroll
        for (int nt = 0; nt < 8; nt++)
            #pragma unroll
            for (int j = 0; j < 4; j++) d[mt][nt][j] = 0.f;

    issue(0);

    #pragma unroll 1
    for (int kt = 0; kt < NKT; ++kt) {
        issue(kt + 1);
        if (kt + 1 < NKT) CP_WAIT1(); else CP_WAIT0();
        __syncthreads();

        uint32_t base = sb + (uint32_t)(kt & 1) * (STAGE_U * 4);
        #pragma unroll
        for (int ks = 0; ks < 2; ks++) {
            uint32_t kby = (uint32_t)(ks * 8 * 4);
            uint32_t ah[2][4], al[2][4];
            #pragma unroll
            for (int mt = 0; mt < 2; mt++) {
                uint32_t aa = base + aoff + (uint32_t)(mt * 16 * RSU * 4) + kby;
                LDSM_X4(ah[mt], aa + PL_AHI * 4);
                LDSM_X4(al[mt], aa + PL_ALO * 4);
            }
            #pragma unroll
            for (int ntp = 0; ntp < 4; ntp++) {
                uint32_t ba = base + boff + (uint32_t)(ntp * 16 * RSU * 4) + kby;
                uint32_t bh[4], bl[4];
                LDSM_X4(bh, ba + PL_BHI * 4);
                LDSM_X4(bl, ba + PL_BLO * 4);
                #pragma unroll
                for (int mt = 0; mt < 2; mt++) {
                    MMA_BF16(d[mt][2*ntp],   ah[mt], bh[0], bh[1]);
                    MMA_BF16(d[mt][2*ntp],   ah[mt], bl[0], bl[1]);
                    MMA_BF16(d[mt][2*ntp],   al[mt], bh[0], bh[1]);
                    MMA_BF16(d[mt][2*ntp+1], ah[mt], bh[2], bh[3]);
                    MMA_BF16(d[mt][2*ntp+1], ah[mt], bl[2], bl[3]);
                    MMA_BF16(d[mt][2*ntp+1], al[mt], bh[2], bh[3]);
                }
            }
        }
        __syncthreads();
    }

    #pragma unroll
    for (int mt = 0; mt < 2; mt++) {
        int row = bm * 128 + wm * 32 + mt * 16 + g;
        #pragma unroll
        for (int nt = 0; nt < 8; nt++) {
            int col = bn * 128 + wn * 64 + nt * 8 + t4 * 2;
            if (col < N) {
                size_t i0 = (size_t)row * N + col;
                size_t i1 = (size_t)(row + 8) * N + col;
                float2 v0 = make_float2(d[mt][nt][0], d[mt][nt][1]);
                float2 v1 = make_float2(d[mt][nt][2], d[mt][nt][3]);
                if (SECOND) {
                    float2 r0v = *(const float2*)(resid + i0);
                    float2 r1v = *(const float2*)(resid + i1);
                    v0.x += r0v.x; v0.y += r0v.y;
                    v1.x += r1v.x; v1.y += r1v.y;
                }
                *(float2*)(Cptr + i0) = v0;
                *(float2*)(Cptr + i1) = v1;
            }
        }
    }
}

// ---------------- block reduction helper -----------------------------------
__device__ __forceinline__ float block_sum256(float v, float* sh) {
    #pragma unroll
    for (int o = 16; o; o >>= 1) v += __shfl_xor_sync(0xffffffffu, v, o);
    int lane = threadIdx.x & 31, wid = threadIdx.x >> 5;
    __syncthreads();
    if (lane == 0) sh[wid] = v;
    __syncthreads();
    float tt = 0.f;
    #pragma unroll
    for (int j = 0; j < 8; j++) tt += sh[j];
    return tt;
}

// ---------------- 1) LayerNorm (writes bf16 hi/lo planes) -------------------
__global__ void __launch_bounds__(256) ln_kernel(const float* __restrict__ x,
                                                 const float* __restrict__ w,
                                                 const float* __restrict__ bparm)
{
    __shared__ float sh[8];
    int row = blockIdx.x, tid = threadIdx.x;
    const float4* xr = (const float4*)(x + (size_t)row * DMODEL);
    float4 v = xr[tid];
    float s  = v.x + v.y + v.z + v.w;
    float mu = block_sum256(s, sh) * (1.f / DMODEL);
    float d0 = v.x - mu, d1 = v.y - mu, d2 = v.z - mu, d3 = v.w - mu;
    float vs = d0*d0 + d1*d1 + d2*d2 + d3*d3;
    float var = block_sum256(vs, sh) * (1.f / DMODEL);
    float inv = rsqrtf(var + 1e-5f);
    float4 wv = ((const float4*)w)[tid];
    float4 bv = ((const float4*)bparm)[tid];
    float4 o;
    o.x = d0 * inv * wv.x + bv.x;
    o.y = d1 * inv * wv.y + bv.y;
    o.z = d2 * inv * wv.z + bv.z;
    o.w = d3 * inv * wv.w + bv.w;
    uint2 hi, lo;
    split4(o, hi, lo);
    size_t idx = (size_t)row * DMODEL + tid * 4;
    *(uint2*)(g_uh + idx) = hi;
    *(uint2*)(g_ul + idx) = lo;
}

// ---------------- 3) rolling-window conv(4)+SiLU + fused dt + BC split ------
// Thread owns one channel for 16 consecutive rows; 3-tap history in regs.
// B/C channels (2048..2175) additionally write bf16 hi/lo straight planes.
__global__ void __launch_bounds__(256) conv_dt_kernel(const float* __restrict__ conv_w,
                                                      const float* __restrict__ conv_b,
                                                      const float* __restrict__ dt_bias)
{
    int c  = blockIdx.x * 256 + threadIdx.x;
    int i0 = blockIdx.y * 16;                 // first global row of tile
    int b  = i0 >> 12;
    int l0 = i0 & 4095;
    if (c < CONVDIM) {
        float w0 = conv_w[c*4+0], w1 = conv_w[c*4+1];
        float w2 = conv_w[c*4+2], w3 = conv_w[c*4+3];
        float bias = conv_b[c];
        bool isbc = (c >= DINNER);
        int bcc = c - DINNER;
        const float* col = g_zx + ((size_t)b << 12) * DINPROJ + DINNER + c;
        float xm3 = (l0 >= 3) ? col[(size_t)(l0-3) * DINPROJ] : 0.f;
        float xm2 = (l0 >= 2) ? col[(size_t)(l0-2) * DINPROJ] : 0.f;
        float xm1 = (l0 >= 1) ? col[(size_t)(l0-1) * DINPROJ] : 0.f;
        #pragma unroll
        for (int j = 0; j < 16; j++) {
            float x0 = col[(size_t)(l0 + j) * DINPROJ];
            float s = bias + xm3 * w0 + xm2 * w1 + xm1 * w2 + x0 * w3;
            s = s / (1.f + expf(-s));
            g_xbca[(size_t)(i0 + j) * CONVDIM + c] = s;
            if (isbc) {
                uint32_t hb = packbf(s, s);
                float l = s - __uint_as_float(hb << 16);
                uint32_t lb = packbf(l, l);
                size_t o = (size_t)(i0 + j) * 128 + bcc;
                g_bcsh[o] = (uint16_t)hb;
                g_bcsl[o] = (uint16_t)lb;
            }
            xm3 = xm2; xm2 = xm1; xm1 = x0;
        }
    } else if (c < CONVDIM + NHEADS) {
        int hh = c - CONVDIM;
        float bias = dt_bias[hh];
        const float* src = g_zx + (size_t)i0 * DINPROJ + (DINNER + CONVDIM) + hh;
        #pragma unroll
        for (int j = 0; j < 16; j++) {
            float v = src[(size_t)j * DINPROJ] + bias;
            g_dt[(size_t)(i0 + j) * NHEADS + hh] = (v > 20.f) ? v : log1pf(expf(v));
        }
    }
}

// ---------------- 3b) B transpose split: B^T [bc][n][t] ---------------------
__global__ void __launch_bounds__(256) btrans_kernel()
{
    __shared__ float sb[64][68];
    int bc = blockIdx.x;                  // b*NCHUNK + chunk (rows bc*64..+63)
    int tid = threadIdx.x;
    const float* src = g_xbca + (size_t)bc * 64 * CONVDIM + 2048;
    #pragma unroll
    for (int i = 0; i < 4; i++) {
        int idx = tid + i * 256;          // 1024 float4 (B region only)
        int t = idx >> 4, c4 = (idx & 15) * 4;
        *(float4*)&sb[t][c4] = *(const float4*)(src + (size_t)t * CONVDIM + c4);
    }
    __syncthreads();
    int n = tid >> 2, tg = (tid & 3) * 16;
    uint32_t hi[8], lo[8];
    #pragma unroll
    for (int j = 0; j < 8; j++)
        split2(sb[tg + 2*j][n], sb[tg + 2*j + 1][n], hi[j], lo[j]);
    size_t o = ((size_t)bc * 64 + n) * 64 + tg;
    *(uint4*)(g_bth + o)     = make_uint4(hi[0], hi[1], hi[2], hi[3]);
    *(uint4*)(g_bth + o + 8) = make_uint4(hi[4], hi[5], hi[6], hi[7]);
    *(uint4*)(g_btl + o)     = make_uint4(lo[0], lo[1], lo[2], lo[3]);
    *(uint4*)(g_btl + o + 8) = make_uint4(lo[4], lo[5], lo[6], lo[7]);
}

// -------- warp-0 inclusive scan of 64 s-values (dt*Ah) -> cum[64] ----------
__device__ __forceinline__ void scan64(const float* dtv, float Ah, float* cum, int tid) {
    if (tid < 32) {
        float a = dtv[tid] * Ah;
        float b = dtv[32 + tid] * Ah;
        #pragma unroll
        for (int o = 1; o < 32; o <<= 1) {
            float ta = __shfl_up_sync(0xffffffffu, a, o);
            float tb = __shfl_up_sync(0xffffffffu, b, o);
            if (tid >= o) { a += ta; b += tb; }
        }
        float totA = __shfl_sync(0xffffffffu, a, 31);
        cum[tid]      = a;
        cum[32 + tid] = totA + b;
    }
}

// ---------------- 4a) S1: chunk-state pass (bf16x3 MMA, pre-split B^T) -----
#define S1_XF    0                          // fp32 X [64][68]
#define S1_BT    4352                       // B^T hi [32 n][36] u32
#define S1_BTLO  5504
#define S1_DT    6656
#define S1_BUF   6720                       // ring buffer (x2)
#define S1_XWT   13440                      // XWT hi [64 p][36] u32
#define S1_XWTLO 15744
#define S1_W     18048
#define S1_CUM   18112
#define S1_SMEMF 18176
#define S1_SMEMB (S1_SMEMF * 4)             // 72704 bytes

__global__ void __launch_bounds__(256) s1_kernel(const float* __restrict__ A_log)
{
    extern __shared__ float sm[];
    uint32_t* su = (uint32_t*)sm;
    int bx = blockIdx.x;
    int b = bx >> 6, h = (bx >> 1) & 31, nh = bx & 1;
    int tid = threadIdx.x;
    int wid = tid >> 5, lane = tid & 31;
    int wm = wid & 1, wn = wid >> 1;        // n-tile (16), p-quarter (16)
    int g = lane >> 2, t4 = lane & 3;
    float Ah = -expf(A_log[h]);

    float* w   = sm + S1_W;
    float* cum = sm + S1_CUM;
    uint32_t sbase = smem_u32(sm);

    const float* base = g_xbca + (size_t)b * SEQLEN * CONVDIM;
    const float* dtb  = g_dt   + (size_t)b * SEQLEN * NHEADS + h;

    auto issue = [&](int c) {
        if (c < NCHUNK) {
            uint32_t dst = sbase + (uint32_t)(c & 1) * (S1_BUF * 4);
            const float* rowb = base + (size_t)c * CHUNK * CONVDIM;
            #pragma unroll
            for (int i = 0; i < 4; i++) {              // X fp32: 1024 f4
                int f4 = tid + i * 256;
                int t = f4 >> 4, j = (f4 & 15) * 4;
                CP_ASYNC16(dst + (uint32_t)(t * 68 + j) * 4,
                           rowb + (size_t)t * CONVDIM + h * 64 + j);
            }
            {                                          // B^T planes
                int n = tid >> 3, ch = tid & 7;
                size_t src = ((size_t)(b * NCHUNK + c) * 64 + nh * 32 + n) * 64 + ch * 8;
                uint32_t so = (uint32_t)(n * 36 + ch * 4) * 4;
                CP_ASYNC16(dst + S1_BT * 4 + so, g_bth + src);
                CP_ASYNC16(dst + S1_BTLO * 4 + so, g_btl + src);
            }
            if (tid < 64)
                CP_ASYNC4(dst + S1_DT * 4 + tid * 4,
                          dtb + (size_t)(c * CHUNK + tid) * NHEADS);
        }
        CP_COMMIT();
    };

    float d0[4] = {0.f, 0.f, 0.f, 0.f};
    float d1[4] = {0.f, 0.f, 0.f, 0.f};

    issue(0); issue(1);

    for (int c = 0; c < NCHUNK; c++) {
        CP_WAIT1();
        __syncthreads();
        float* S = sm + (c & 1) * S1_BUF;
        uint32_t* SU = su + (c & 1) * S1_BUF;

        scan64(S + S1_DT, Ah, cum, tid);
        __syncthreads();

        float cl = cum[63];
        float E  = expf(cl);
        if (tid < 64) w[tid] = expf(cl - cum[tid]) * S[S1_DT + tid];

        // carry store (state at chunk start) as bf16 hi/lo planes [p][n]
        {
            size_t hcb = (((size_t)(b * 32 + h)) * NCHUNK + c) * 4096;
            int n0 = nh * 32 + wm * 16 + g;
            int p0 = wn * 16 + 2 * t4;
            auto stbf = [&](int p, int n, float v) {
                uint32_t hb = packbf(v, v);
                float l = v - __uint_as_float(hb << 16);
                uint32_t lb = packbf(l, l);
                size_t a = hcb + (size_t)p * 64 + n;
                g_hch[a] = (uint16_t)hb;
                g_hcl[a] = (uint16_t)lb;
            };
            stbf(p0,     n0,     d0[0]); stbf(p0 + 1, n0,     d0[1]);
            stbf(p0,     n0 + 8, d0[2]); stbf(p0 + 1, n0 + 8, d0[3]);
            stbf(p0 + 8, n0,     d1[0]); stbf(p0 + 9, n0,     d1[1]);
            stbf(p0 + 8, n0 + 8, d1[2]); stbf(p0 + 9, n0 + 8, d1[3]);
        }
        #pragma unroll
        for (int j = 0; j < 4; j++) { d0[j] *= E; d1[j] *= E; }
        __syncthreads();                      // w ready; prev XWT reads done

        // build XWT planes: [p][t-pairs], value = w_t * X[t][p]
        {
            int p = tid & 63, tq = tid >> 6;
            uint32_t hi[8], lo[8];
            #pragma unroll
            for (int q = 0; q < 8; q++) {
                int t0 = tq * 16 + 2 * q;
                float a = S[t0 * 68 + p] * w[t0];
                float bb = S[(t0 + 1) * 68 + p] * w[t0 + 1];
                split2(a, bb, hi[q], lo[q]);
            }
            int o = S1_XWT + p * 36 + tq * 8;
            *(uint4*)&su[o]            = make_uint4(hi[0], hi[1], hi[2], hi[3]);
            *(uint4*)&su[o + 4]        = make_uint4(hi[4], hi[5], hi[6], hi[7]);
            *(uint4*)&su[o + 2304]     = make_uint4(lo[0], lo[1], lo[2], lo[3]);
            *(uint4*)&su[o + 2304 + 4] = make_uint4(lo[4], lo[5], lo[6], lo[7]);
        }
        __syncthreads();                      // XWT ready

        // MMA: dd[pb] += B^T(n,t) x XWT(p,t)^T
        const uint32_t* BT = SU + S1_BT;
        #pragma unroll
        for (int kc = 0; kc < 4; kc++) {
            int o0 = (wm * 16 + g) * 36 + kc * 8 + t4;
            int o1 = o0 + 8 * 36;
            uint32_t ah[4], al[4];
            ah[0] = BT[o0];     ah[1] = BT[o1];
            ah[2] = BT[o0 + 4]; ah[3] = BT[o1 + 4];
            al[0] = BT[1152 + o0];     al[1] = BT[1152 + o1];
            al[2] = BT[1152 + o0 + 4]; al[3] = BT[1152 + o1 + 4];
            #pragma unroll
            for (int pb = 0; pb < 2; pb++) {
                int pr = S1_XWT + (wn * 16 + pb * 8 + g) * 36 + kc * 8 + t4;
                uint32_t bh0 = su[pr], bh1 = su[pr + 4];
                uint32_t bl0 = su[pr + 2304], bl1 = su[pr + 2304 + 4];
                float* dd = pb ? d1 : d0;
                MMA_BF16(dd, ah, bh0, bh1);
                MMA_BF16(dd, ah, bl0, bl1);
                MMA_BF16(dd, al, bh0, bh1);
            }
        }
        __syncthreads();                      // reads done before restage
        issue(c + 2);
    }
}

// ---------------- 4b) S2: per-chunk parallel y (bf16x3 MMA, pre-split) ------
#define P_A     0          // C hi (later G hi)
#define P_ALO   2304
#define P_B     4608
#define P_BLO   6912
#define P_C2    9216
#define P_C2LO  11520
#define P_XT    13824
#define P_XTLO  16128
#define P_HT    18432
#define P_HTLO  20736
#define P_XF    23040      // fp32 X tile [64][68]
#define P_DT2   27392
#define P_CUM2  27456
#define S2N_U   27520
#define S2N_B   (S2N_U * 4)   // 110080 bytes

__global__ void __launch_bounds__(256) s2_kernel(const float* __restrict__ A_log,
                                                 const float* __restrict__ Dp)
{
    extern __shared__ uint32_t su[];
    float* sf = (float*)su;
    int bx = blockIdx.x;
    int c = bx & 63, h = (bx >> 6) & 31, b = bx >> 11;
    int tid = threadIdx.x;
    int wid = tid >> 5, lane = tid & 31;
    int wm = wid >> 1, wn = wid & 1;        // 4x2 warp grid, warp tile 16x32
    int g = lane >> 2, t4 = lane & 3;
    float Ah = -expf(A_log[h]);
    float Dh = Dp[h];

    uint32_t sb = smem_u32(su);
    const float* rowb = g_xbca + ((size_t)b * SEQLEN + c * 64) * CONVDIM;

    // ---- async loads: C/B planes, HT planes, X fp32, dt --------------------
    {
        int r = tid >> 2, q = tid & 3;
        size_t ib = ((size_t)(b * SEQLEN + c * 64 + r)) * 128;
        size_t hb = (((size_t)(b * 32 + h)) * NCHUNK + c) * 4096 + (size_t)r * 64;
        #pragma unroll
        for (int k = 0; k < 2; k++) {
            int ch = q * 2 + k;
            uint32_t so = (uint32_t)(r * 36 + ch * 4) * 4;
            CP_ASYNC16(sb + P_A * 4 + so,    g_bcsh + ib + 64 + ch * 8);
            CP_ASYNC16(sb + P_ALO * 4 + so,  g_bcsl + ib + 64 + ch * 8);
            CP_ASYNC16(sb + P_B * 4 + so,    g_bcsh + ib + ch * 8);
            CP_ASYNC16(sb + P_BLO * 4 + so,  g_bcsl + ib + ch * 8);
            CP_ASYNC16(sb + P_HT * 4 + so,   g_hch + hb + ch * 8);
            CP_ASYNC16(sb + P_HTLO * 4 + so, g_hcl + hb + ch * 8);
        }
        #pragma unroll
        for (int i = 0; i < 4; i++) {
            int f4 = tid + i * 256;
            int t = f4 >> 4, j = (f4 & 15) * 4;
            CP_ASYNC16(sb + (uint32_t)(P_XF + t * 68 + j) * 4,
                       rowb + (size_t)t * CONVDIM + h * 64 + j);
        }
        if (tid < 64)
            CP_ASYNC4(sb + (uint32_t)(P_DT2 + tid) * 4,
                      g_dt + ((size_t)b * SEQLEN + c * 64 + tid) * NHEADS + h);
        CP_COMMIT();
    }

    // fp32 C rows for C2 (independent regular loads)
    int r = tid >> 2;
    int cg = (tid & 3) * 16;
    float4 cre[4];
    #pragma unroll
    for (int i = 0; i < 4; i++)
        cre[i] = *(const float4*)(rowb + (size_t)r * CONVDIM + 2112 + cg + 4 * i);

    CP_WAIT0();
    __syncthreads();

    scan64(sf + P_DT2, Ah, sf + P_CUM2, tid);
    __syncthreads();

    // ---- C2 = Et*C planes, XT planes ---------------------------------------
    {
        float Et = expf(sf[P_CUM2 + r]);
        #pragma unroll
        for (int i = 0; i < 4; i++) {
            float4 v = cre[i];
            v.x *= Et; v.y *= Et; v.z *= Et; v.w *= Et;
            uint2 hi, lo;
            split4(v, hi, lo);
            int col = cg + 4 * i;
            *(uint2*)&su[P_C2 + r * 36 + col / 2]          = hi;
            *(uint2*)&su[P_C2 + 2304 + r * 36 + col / 2]   = lo;
        }
    }
    {
        int p = tid & 63, tq = tid >> 6;
        uint32_t hi[8], lo[8];
        #pragma unroll
        for (int q = 0; q < 8; q++) {
            int t0 = tq * 16 + 2 * q;
            split2(sf[P_XF + t0 * 68 + p], sf[P_XF + (t0 + 1) * 68 + p], hi[q], lo[q]);
        }
        int o = P_XT + p * 36 + tq * 8;
        *(uint4*)&su[o]            = make_uint4(hi[0], hi[1], hi[2], hi[3]);
        *(uint4*)&su[o + 4]        = make_uint4(hi[4], hi[5], hi[6], hi[7]);
        *(uint4*)&su[o + 2304]     = make_uint4(lo[0], lo[1], lo[2], lo[3]);
        *(uint4*)&su[o + 2304 + 4] = make_uint4(lo[4], lo[5], lo[6], lo[7]);
    }
    __syncthreads();

    auto mm = [&](uint32_t offA, uint32_t offB, float (*dd)[4]) {
        #pragma unroll
        for (int ks = 0; ks < 4; ks++) {
            int kb = ks * 8;
            uint32_t ah[4], al[4];
            int o0 = (wm * 16 + g) * 36 + kb + t4;
            int o1 = o0 + 8 * 36;
            ah[0] = su[offA + o0];     ah[1] = su[offA + o1];
            ah[2] = su[offA + o0 + 4]; ah[3] = su[offA + o1 + 4];
            al[0] = su[offA + 2304 + o0];     al[1] = su[offA + 2304 + o1];
            al[2] = su[offA + 2304 + o0 + 4]; al[3] = su[offA + 2304 + o1 + 4];
            #pragma unroll
            for (int nt = 0; nt < 4; nt++) {
                int ob = (wn * 32 + nt * 8 + g) * 36 + kb + t4;
                uint32_t bh0 = su[offB + ob], bh1 = su[offB + ob + 4];
                uint32_t bl0 = su[offB + 2304 + ob], bl1 = su[offB + 2304 + ob + 4];
                MMA_BF16(dd[nt], ah, bh0, bh1);
                MMA_BF16(dd[nt], ah, bl0, bl1);
                MMA_BF16(dd[nt], al, bh0, bh1);
            }
        }
    };

    float d[4][4];
    #pragma unroll
    for (int nt = 0; nt < 4; nt++)
        #pragma unroll
        for (int j = 0; j < 4; j++) d[nt][j] = 0.f;
    // causal skip: warps whose t-range lies entirely below s-range have G==0
    if (wm * 16 + 15 >= wn * 32)
        mm(P_A, P_B, d);

    int t0 = wm * 16 + g, t1 = t0 + 8;
    float ct0 = sf[P_CUM2 + t0], ct1 = sf[P_CUM2 + t1];
    float gv[4][4];
    #pragma unroll
    for (int nt = 0; nt < 4; nt++) {
        int s0 = wn * 32 + nt * 8 + 2 * t4, s1 = s0 + 1;
        float cs0 = sf[P_CUM2 + s0], cs1 = sf[P_CUM2 + s1];
        float w0 = sf[P_DT2 + s0],  w1 = sf[P_DT2 + s1];
        gv[nt][0] = (s0 <= t0) ? d[nt][0] * expf(ct0 - cs0) * w0 : 0.f;
        gv[nt][1] = (s1 <= t0) ? d[nt][1] * expf(ct0 - cs1) * w1 : 0.f;
        gv[nt][2] = (s0 <= t1) ? d[nt][2] * expf(ct1 - cs0) * w0 : 0.f;
        gv[nt][3] = (s1 <= t1) ? d[nt][3] * expf(ct1 - cs1) * w1 : 0.f;
    }
    __syncthreads();

    #pragma unroll
    for (int nt = 0; nt < 4; nt++) {
        int pi = wn * 16 + nt * 4 + t4;
        uint32_t h01, l01, h23, l23;
        split2(gv[nt][0], gv[nt][1], h01, l01);
        split2(gv[nt][2], gv[nt][3], h23, l23);
        su[P_A   + t0 * 36 + pi] = h01;
        su[P_ALO + t0 * 36 + pi] = l01;
        su[P_A   + t1 * 36 + pi] = h23;
        su[P_ALO + t1 * 36 + pi] = l23;
    }
    __syncthreads();

    #pragma unroll
    for (int nt = 0; nt < 4; nt++)
        #pragma unroll
        for (int j = 0; j < 4; j++) d[nt][j] = 0.f;
    mm(P_A, P_XT, d);
    mm(P_C2, P_HT, d);

    float* yo = g_y + ((size_t)b * SEQLEN + c * 64) * DINNER + h * 64;
    #pragma unroll
    for (int nt = 0; nt < 4; nt++) {
        int p0 = wn * 32 + nt * 8 + 2 * t4;
        float2 x0 = *(const float2*)&sf[P_XF + t0 * 68 + p0];
        float2 x1 = *(const float2*)&sf[P_XF + t1 * 68 + p0];
        float2 v0 = make_float2(d[nt][0] + Dh * x0.x, d[nt][1] + Dh * x0.y);
        float2 v1 = make_float2(d[nt][2] + Dh * x1.x, d[nt][3] + Dh * x1.y);
        *(float2*)&yo[(size_t)t0 * DINNER + p0] = v0;
        *(float2*)&yo[(size_t)t1 * DINNER + p0] = v1;
    }
}

// ---------------- 5) gate + RMSNorm (writes bf16 hi/lo planes) --------------
__global__ void __launch_bounds__(256) gate_rms_kernel(const float* __restrict__ norm_w)
{
    __shared__ float sh[8];
    int row = blockIdx.x, tid = threadIdx.x;
    const float4* y4 = (const float4*)(g_y  + (size_t)row * DINNER);
    const float4* z4 = (const float4*)(g_zx + (size_t)row * DINPROJ);
    float4 a0 = y4[tid], a1 = y4[tid + 256];
    float4 z0 = z4[tid], z1 = z4[tid + 256];
    float g[8];
    g[0] = a0.x * (z0.x / (1.f + expf(-z0.x)));
    g[1] = a0.y * (z0.y / (1.f + expf(-z0.y)));
    g[2] = a0.z * (z0.z / (1.f + expf(-z0.z)));
    g[3] = a0.w * (z0.w / (1.f + expf(-z0.w)));
    g[4] = a1.x * (z1.x / (1.f + expf(-z1.x)));
    g[5] = a1.y * (z1.y / (1.f + expf(-z1.y)));
    g[6] = a1.z * (z1.z / (1.f + expf(-z1.z)));
    g[7] = a1.w * (z1.w / (1.f + expf(-z1.w)));
    float ss = 0.f;
    #pragma unroll
    for (int j = 0; j < 8; j++) ss += g[j] * g[j];
    float tot = block_sum256(ss, sh);
    float inv = rsqrtf(tot * (1.f / DINNER) + 1e-5f);
    float4 w0 = ((const float4*)norm_w)[tid];
    float4 w1 = ((const float4*)norm_w)[tid + 256];
    float4 o0, o1;
    o0.x = g[0] * inv * w0.x; o0.y = g[1] * inv * w0.y;
    o0.z = g[2] * inv * w0.z; o0.w = g[3] * inv * w0.w;
    o1.x = g[4] * inv * w1.x; o1.y = g[5] * inv * w1.y;
    o1.z = g[6] * inv * w1.z; o1.w = g[7] * inv * w1.w;
    uint2 hi, lo;
    size_t idx = (size_t)row * DINNER + tid * 4;
    split4(o0, hi, lo);
    *(uint2*)(g_ynh + idx) = hi;
    *(uint2*)(g_ynl + idx) = lo;
    split4(o1, hi, lo);
    *(uint2*)(g_ynh + idx + 1024) = hi;
    *(uint2*)(g_ynl + idx + 1024) = lo;
}

// ---------------- launcher -------------------------------------------------
extern "C" void kernel_launch(void* const* d_in, const int* in_sizes, int n_in,
                              void* d_out, int out_size)
{
    const float* x       = (const float*)d_in[0];
    const float* ln_w    = (const float*)d_in[1];
    const float* ln_b    = (const float*)d_in[2];
    const float* W_in    = (const float*)d_in[3];
    const float* conv_w  = (const float*)d_in[4];
    const float* conv_b  = (const float*)d_in[5];
    const float* dt_bias = (const float*)d_in[6];
    const float* A_log   = (const float*)d_in[7];
    const float* Dp      = (const float*)d_in[8];
    const float* norm_w  = (const float*)d_in[9];
    const float* W_out   = (const float*)d_in[10];
    float* out = (float*)d_out;

    cudaFuncSetAttribute(gemm_tc<DINPROJ, DMODEL, false>,
                         cudaFuncAttributeMaxDynamicSharedMemorySize, SMEM_DYN);
    cudaFuncSetAttribute(gemm_tc<DMODEL, DINNER, true>,
                         cudaFuncAttributeMaxDynamicSharedMemorySize, SMEM_DYN);
    cudaFuncSetAttribute(s1_kernel,
                         cudaFuncAttributeMaxDynamicSharedMemorySize, S1_SMEMB);
    cudaFuncSetAttribute(s2_kernel,
                         cudaFuncAttributeMaxDynamicSharedMemorySize, S2N_B);

    uint16_t *wih, *wil, *woh, *wol;
    cudaGetSymbolAddress((void**)&wih, g_wih);
    cudaGetSymbolAddress((void**)&wil, g_wil);
    cudaGetSymbolAddress((void**)&woh, g_woh);
    cudaGetSymbolAddress((void**)&wol, g_wol);

    wsplit_kernel<<<(DINPROJ * DMODEL / 4 + 255) / 256, 256>>>(W_in, wih, wil,
                                                               DINPROJ * DMODEL / 4); // 1
    ln_kernel<<<BL, 256>>>(x, ln_w, ln_b);                          // 2

    gemm_tc<DINPROJ, DMODEL, false>                                 // 3
        <<<dim3((DINPROJ + 127) / 128, BL / 128), 256, SMEM_DYN>>>(nullptr, nullptr);

    conv_dt_kernel<<<dim3(9, BL / 16), 256>>>(conv_w, conv_b, dt_bias); // 4 <- ncu window

    wsplit_kernel<<<(DMODEL * DINNER / 4 + 255) / 256, 256>>>(W_out, woh, wol,
                                                              DMODEL * DINNER / 4);   // 5

    btrans_kernel<<<BATCH * NCHUNK, 256>>>();                       // 6

    s1_kernel<<<BATCH * NHEADS * 2, 256, S1_SMEMB>>>(A_log);        // 7

    s2_kernel<<<BATCH * NHEADS * NCHUNK, 256, S2N_B>>>(A_log, Dp);  // 8

    gate_rms_kernel<<<BL, 256>>>(norm_w);                           // 9

    gemm_tc<DMODEL, DINNER, true>                                   // 10
        <<<dim3(DMODEL / 128, BL / 128), 256, SMEM_DYN>>>(x, out);
}